// round 2
// baseline (speedup 1.0000x reference)
#include <cuda_runtime.h>
#include <cuda_bf16.h>
#include <math.h>

// Problem constants
#define B_SZ 512
#define T_SZ 64
#define I_SZ 64
#define H_SZ 128
#define G_SZ 384   // 3*H

// ---------------- device scratch (no allocations allowed) ----------------
__device__ float g_P [I_SZ * H_SZ * G_SZ];          // packed W_hh: [i][k][lane][12]
__device__ float g_hs[B_SZ * I_SZ * H_SZ];          // GRU final hidden (then reused for V)
__device__ float g_A [B_SZ * I_SZ * H_SZ];          // scratch
__device__ float g_B [B_SZ * I_SZ * H_SZ];          // scratch (ctx)
__device__ float g_Wt[7 * H_SZ * H_SZ];             // transposed weights: fp,g1,g2,wk,wv,wq,out0

// ---------------- pack W_hh ----------------
// P[((i*128 + k)*32 + l)*12 + c*3 + s] = W_hh[i][s*128 + l + 32c][k]
__global__ void pack_whh_kernel(const float* __restrict__ W_hh, float* __restrict__ P)
{
    int idx = blockIdx.x * blockDim.x + threadIdx.x;
    if (idx >= I_SZ * H_SZ * G_SZ) return;
    int tmp = idx;
    int m = tmp % 12; tmp /= 12;
    int l = tmp % 32; tmp /= 32;
    int k = tmp % 128; tmp /= 128;
    int i = tmp;
    int c = m / 3, s = m % 3;
    int g = s * 128 + l + 32 * c;
    P[idx] = W_hh[((size_t)i * G_SZ + g) * H_SZ + k];
}

// ---------------- transpose the 7 [H,H] weight matrices ----------------
__global__ void transpose7_kernel(const float* __restrict__ fp, const float* __restrict__ g1,
                                  const float* __restrict__ g2, const float* __restrict__ wk,
                                  const float* __restrict__ wv, const float* __restrict__ wq,
                                  const float* __restrict__ o0, float* __restrict__ out)
{
    int idx = blockIdx.x * blockDim.x + threadIdx.x;
    if (idx >= 7 * H_SZ * H_SZ) return;
    int w = idx >> 14;
    int r = idx & 16383;
    int k = r >> 7, n = r & 127;
    const float* src = (w == 0) ? fp : (w == 1) ? g1 : (w == 2) ? g2 :
                       (w == 3) ? wk : (w == 4) ? wv : (w == 5) ? wq : o0;
    out[idx] = src[n * 128 + k];   // out[w][k][n] = W[n][k]
}

// ---------------- GRU scan ----------------
// grid = (8 batch-blocks, 64 features), block = 512 threads (16 warps)
// warp w -> 4 batches, lane l -> 4 hidden indices {l, l+32, l+64, l+96}
__global__ __launch_bounds__(512) void gru_kernel(
    const float* __restrict__ x,      // [B][T][I]
    const float* __restrict__ P,      // packed W_hh
    const float* __restrict__ W_ih,   // [I][3H]
    const float* __restrict__ b_ih,   // [I][3H]
    const float* __restrict__ b_hh,   // [I][3H]
    float* __restrict__ hs_out)       // [B][I][H]
{
    __shared__ float hsm[64][128];       // h state for 64 batches
    __shared__ float wih_s[G_SZ], bih_s[G_SZ], bhh_s[G_SZ];

    const int i  = blockIdx.y;
    const int b0 = blockIdx.x * 64;
    const int tid = threadIdx.x;
    const int w = tid >> 5, l = tid & 31;
    const int bloc = w * 4;              // local batch base for this warp

    for (int idx = tid; idx < G_SZ; idx += 512) {
        wih_s[idx] = W_ih[i * G_SZ + idx];
        bih_s[idx] = b_ih[i * G_SZ + idx];
        bhh_s[idx] = b_hh[i * G_SZ + idx];
    }
    for (int idx = tid; idx < 64 * 128; idx += 512)
        ((float*)hsm)[idx] = 0.0f;
    __syncthreads();

    const float4* Pi = (const float4*)(P + (size_t)i * H_SZ * G_SZ);

    for (int t = 0; t < T_SZ; t++) {
        float ar[4][4], az[4][4], an[4][4];
#pragma unroll
        for (int bb = 0; bb < 4; bb++)
#pragma unroll
            for (int c = 0; c < 4; c++) { ar[bb][c] = 0.f; az[bb][c] = 0.f; an[bb][c] = 0.f; }

#pragma unroll 4
        for (int k = 0; k < 128; k++) {
            const float4 w0 = Pi[(k * 32 + l) * 3 + 0];
            const float4 w1 = Pi[(k * 32 + l) * 3 + 1];
            const float4 w2 = Pi[(k * 32 + l) * 3 + 2];
            float wv[12];
            wv[0]=w0.x; wv[1]=w0.y; wv[2]=w0.z; wv[3]=w0.w;
            wv[4]=w1.x; wv[5]=w1.y; wv[6]=w1.z; wv[7]=w1.w;
            wv[8]=w2.x; wv[9]=w2.y; wv[10]=w2.z; wv[11]=w2.w;
            float hv[4];
#pragma unroll
            for (int bb = 0; bb < 4; bb++) hv[bb] = hsm[bloc + bb][k];
#pragma unroll
            for (int bb = 0; bb < 4; bb++) {
#pragma unroll
                for (int c = 0; c < 4; c++) {
                    ar[bb][c] = fmaf(hv[bb], wv[c * 3 + 0], ar[bb][c]);
                    az[bb][c] = fmaf(hv[bb], wv[c * 3 + 1], az[bb][c]);
                    an[bb][c] = fmaf(hv[bb], wv[c * 3 + 2], an[bb][c]);
                }
            }
        }

        // epilogue: gates + state update
        float hnew[4][4];
#pragma unroll
        for (int bb = 0; bb < 4; bb++) {
            const int bglob = b0 + bloc + bb;
            const float xt = __ldg(&x[(size_t)bglob * (T_SZ * I_SZ) + t * I_SZ + i]);
#pragma unroll
            for (int c = 0; c < 4; c++) {
                const int j = l + 32 * c;
                const float ir  = fmaf(xt, wih_s[j      ], bih_s[j      ]);
                const float iz  = fmaf(xt, wih_s[j + 128], bih_s[j + 128]);
                const float inn = fmaf(xt, wih_s[j + 256], bih_s[j + 256]);
                const float hr = ar[bb][c] + bhh_s[j      ];
                const float hz = az[bb][c] + bhh_s[j + 128];
                const float hn = an[bb][c] + bhh_s[j + 256];
                const float r = 1.0f / (1.0f + __expf(-(ir + hr)));
                const float z = 1.0f / (1.0f + __expf(-(iz + hz)));
                const float n = tanhf(inn + r * hn);
                const float hold = hsm[bloc + bb][j];
                hnew[bb][c] = (1.0f - z) * n + z * hold;
            }
        }
        __syncthreads();   // everyone done reading hsm
#pragma unroll
        for (int bb = 0; bb < 4; bb++)
#pragma unroll
            for (int c = 0; c < 4; c++)
                hsm[bloc + bb][l + 32 * c] = hnew[bb][c];
        __syncthreads();
    }

    // write out final hidden state: hs[b][i][h]
    for (int idx = tid; idx < 64 * 128; idx += 512) {
        int b = idx >> 7, h = idx & 127;
        hs_out[((size_t)(b0 + b) * I_SZ + i) * H_SZ + h] = hsm[b][h];
    }
}

// ---------------- generic linear: Y[m][n] = X[m][:] . W[n][:] + b[n] ----------------
// Wt is pre-transposed: Wt[k][n]. grid = M/64, block = 256.
__global__ __launch_bounds__(256) void lin_kernel(
    const float* __restrict__ X, const float* __restrict__ Wt,
    const float* __restrict__ bias, float* __restrict__ Y, int relu)
{
    __shared__ float Xs[64][128];
    const int m0 = blockIdx.x * 64;
    const int tid = threadIdx.x, w = tid >> 5, l = tid & 31;
    for (int idx = tid; idx < 64 * 128; idx += 256)
        Xs[idx >> 7][idx & 127] = X[(size_t)m0 * 128 + idx];
    __syncthreads();

    float acc[8][4];
#pragma unroll
    for (int rr = 0; rr < 8; rr++)
#pragma unroll
        for (int c = 0; c < 4; c++) acc[rr][c] = 0.f;

    const int r0 = w * 8;
#pragma unroll 4
    for (int k = 0; k < 128; k++) {
        float wv[4];
#pragma unroll
        for (int c = 0; c < 4; c++) wv[c] = __ldg(&Wt[k * 128 + l + 32 * c]);
#pragma unroll
        for (int rr = 0; rr < 8; rr++) {
            const float xv = Xs[r0 + rr][k];
#pragma unroll
            for (int c = 0; c < 4; c++) acc[rr][c] = fmaf(xv, wv[c], acc[rr][c]);
        }
    }
#pragma unroll
    for (int rr = 0; rr < 8; rr++)
#pragma unroll
        for (int c = 0; c < 4; c++) {
            const int n = l + 32 * c;
            float v = acc[rr][c] + __ldg(&bias[n]);
            if (relu) v = fmaxf(v, 0.f);
            Y[(size_t)(m0 + r0 + rr) * 128 + n] = v;
        }
}

// ---------------- adjacency conv: Y[b][i][h] = sum_j adj[i][j] * X[b][j][h] ----------------
__global__ __launch_bounds__(256) void adjmul_kernel(
    const float* __restrict__ X, const float* __restrict__ adj, float* __restrict__ Y)
{
    __shared__ float Xs[64][128];
    const int b = blockIdx.x;
    const int tid = threadIdx.x, w = tid >> 5, l = tid & 31;
    for (int idx = tid; idx < 64 * 128; idx += 256)
        Xs[idx >> 7][idx & 127] = X[(size_t)b * 8192 + idx];
    __syncthreads();

    float acc[8][4];
#pragma unroll
    for (int ii = 0; ii < 8; ii++)
#pragma unroll
        for (int c = 0; c < 4; c++) acc[ii][c] = 0.f;

    const int i0 = w * 8;
#pragma unroll 4
    for (int j = 0; j < 64; j++) {
        float hv[4];
#pragma unroll
        for (int c = 0; c < 4; c++) hv[c] = Xs[j][l + 32 * c];
#pragma unroll
        for (int ii = 0; ii < 8; ii++) {
            const float a = __ldg(&adj[(i0 + ii) * 64 + j]);
#pragma unroll
            for (int c = 0; c < 4; c++) acc[ii][c] = fmaf(a, hv[c], acc[ii][c]);
        }
    }
#pragma unroll
    for (int ii = 0; ii < 8; ii++)
#pragma unroll
        for (int c = 0; c < 4; c++)
            Y[(size_t)b * 8192 + (i0 + ii) * 128 + l + 32 * c] = acc[ii][c];
}

// ---------------- attention + output head ----------------
// block per batch, 128 threads
__global__ __launch_bounds__(128) void attn_kernel(
    const float* __restrict__ ctx,   // [B][I][H]
    const float* __restrict__ K,     // [B][I][H]
    const float* __restrict__ V,     // [B][I][H]
    const float* __restrict__ wqT,   // [k][n]
    const float* __restrict__ wq_b,
    const float* __restrict__ o0T,   // [k][n]
    const float* __restrict__ o0_b,
    float* __restrict__ out)         // [B][H]
{
    __shared__ float ctxl[128], qv[128], ev[64], red[2], wc[128];
    const int b = blockIdx.x, t = threadIdx.x;

    ctxl[t] = ctx[(size_t)b * 8192 + 63 * 128 + t];
    __syncthreads();

    float s = __ldg(&wq_b[t]);
    for (int k = 0; k < 128; k++) s = fmaf(ctxl[k], __ldg(&wqT[k * 128 + t]), s);
    qv[t] = s;
    __syncthreads();

    if (t < 64) {
        float e = 0.f;
        const float* Kp = K + (size_t)b * 8192 + t * 128;
        for (int h = 0; h < 128; h++) e = fmaf(Kp[h], qv[h], e);
        ev[t] = e;
    }
    __syncthreads();
    if (t == 0) {
        float mx = -1e30f;
        for (int ii = 0; ii < 64; ii++) mx = fmaxf(mx, ev[ii]);
        float sm = 0.f;
        for (int ii = 0; ii < 64; ii++) sm += __expf(ev[ii] - mx);
        red[0] = mx; red[1] = 1.0f / sm;
    }
    __syncthreads();
    if (t < 64) ev[t] = __expf(ev[t] - red[0]) * red[1];
    __syncthreads();

    float acc = 0.f;
    for (int ii = 0; ii < 64; ii++)
        acc = fmaf(ev[ii], V[(size_t)b * 8192 + ii * 128 + t], acc);
    wc[t] = acc;
    __syncthreads();

    float o = __ldg(&o0_b[t]);
    for (int h = 0; h < 128; h++) o = fmaf(wc[h], __ldg(&o0T[h * 128 + t]), o);
    out[(size_t)b * 128 + t] = fmaxf(o, 0.f);
}

// ---------------- launch ----------------
extern "C" void kernel_launch(void* const* d_in, const int* in_sizes, int n_in,
                              void* d_out, int out_size)
{
    const float* x     = (const float*)d_in[0];
    const float* W_ih  = (const float*)d_in[1];
    const float* W_hh  = (const float*)d_in[2];
    const float* b_ih  = (const float*)d_in[3];
    const float* b_hh  = (const float*)d_in[4];
    const float* fp_w  = (const float*)d_in[5];
    const float* fp_b  = (const float*)d_in[6];
    const float* g1_w  = (const float*)d_in[7];
    const float* g1_b  = (const float*)d_in[8];
    const float* g2_w  = (const float*)d_in[9];
    const float* g2_b  = (const float*)d_in[10];
    const float* wq_w  = (const float*)d_in[11];
    const float* wq_b  = (const float*)d_in[12];
    const float* wk_w  = (const float*)d_in[13];
    const float* wk_b  = (const float*)d_in[14];
    const float* wv_w  = (const float*)d_in[15];
    const float* wv_b  = (const float*)d_in[16];
    const float* o0_w  = (const float*)d_in[17];
    const float* o0_b  = (const float*)d_in[18];
    const float* adj   = (const float*)d_in[19];

    float* out = (float*)d_out;
    float* ht_out = out + B_SZ * H_SZ;   // ht lives in d_out directly

    float *P, *hs, *A, *Bf, *Wt;
    cudaGetSymbolAddress((void**)&P,  g_P);
    cudaGetSymbolAddress((void**)&hs, g_hs);
    cudaGetSymbolAddress((void**)&A,  g_A);
    cudaGetSymbolAddress((void**)&Bf, g_B);
    cudaGetSymbolAddress((void**)&Wt, g_Wt);

    // prep
    {
        int n = I_SZ * H_SZ * G_SZ;
        pack_whh_kernel<<<(n + 255) / 256, 256>>>(W_hh, P);
    }
    {
        int n = 7 * H_SZ * H_SZ;
        transpose7_kernel<<<(n + 255) / 256, 256>>>(fp_w, g1_w, g2_w, wk_w, wv_w, wq_w, o0_w, Wt);
    }

    const float* fpT = Wt + 0 * 16384;
    const float* g1T = Wt + 1 * 16384;
    const float* g2T = Wt + 2 * 16384;
    const float* wkT = Wt + 3 * 16384;
    const float* wvT = Wt + 4 * 16384;
    const float* wqT = Wt + 5 * 16384;
    const float* o0T = Wt + 6 * 16384;

    // 1) GRU scan -> hs
    gru_kernel<<<dim3(8, 64), 512>>>(x, P, W_ih, b_ih, b_hh, hs);

    const int M = B_SZ * I_SZ;   // 32768 rows
    // 2) ht = hs @ fp^T + b  (written straight into d_out)
    lin_kernel<<<M / 64, 256>>>(hs, fpT, fp_b, ht_out, 0);
    // 3) g = relu((adj @ ht) @ g1^T + b1)
    adjmul_kernel<<<B_SZ, 256>>>(ht_out, adj, A);
    lin_kernel<<<M / 64, 256>>>(A, g1T, g1_b, Bf, 1);
    // 4) ctx = relu((adj @ g) @ g2^T + b2)
    adjmul_kernel<<<B_SZ, 256>>>(Bf, adj, A);
    lin_kernel<<<M / 64, 256>>>(A, g2T, g2_b, Bf, 1);   // Bf = ctx
    // 5) K, V
    lin_kernel<<<M / 64, 256>>>(Bf, wkT, wk_b, A, 0);   // A = K
    lin_kernel<<<M / 64, 256>>>(Bf, wvT, wv_b, hs, 0);  // hs = V (reuse)
    // 6) attention + output head
    attn_kernel<<<B_SZ, 128>>>(Bf, A, hs, wqT, wq_b, o0T, o0_b, out);
}

// round 4
// speedup vs baseline: 4.3442x; 4.3442x over previous
#include <cuda_runtime.h>
#include <cuda_bf16.h>
#include <math.h>
#include <stdint.h>

// Problem constants
#define B_SZ 512
#define T_SZ 64
#define I_SZ 64
#define H_SZ 128
#define G_SZ 384   // 3*H

// ---------------- device scratch (no allocations allowed) ----------------
__device__ float g_P [I_SZ * G_SZ * H_SZ];          // per-feature W_hh, B-fragment-layout tf32
__device__ float g_hs[B_SZ * I_SZ * H_SZ];          // GRU final hidden (then reused for V)
__device__ float g_A [B_SZ * I_SZ * H_SZ];          // scratch
__device__ float g_B [B_SZ * I_SZ * H_SZ];          // scratch (ctx)
__device__ float g_Wt[7 * H_SZ * H_SZ];             // transposed tail weights

__device__ __forceinline__ uint32_t tf32_bits(float v) {
    uint32_t o;
    asm("cvt.rna.tf32.f32 %0, %1;" : "=r"(o) : "f"(v));
    return o;
}

__device__ __forceinline__ void mma_tf32(float* d, const uint32_t* a, uint32_t b0, uint32_t b1) {
    asm volatile(
        "mma.sync.aligned.m16n8k8.row.col.f32.tf32.tf32.f32 "
        "{%0,%1,%2,%3}, {%4,%5,%6,%7}, {%8,%9}, {%0,%1,%2,%3};"
        : "+f"(d[0]), "+f"(d[1]), "+f"(d[2]), "+f"(d[3])
        : "r"(a[0]), "r"(a[1]), "r"(a[2]), "r"(a[3]), "r"(b0), "r"(b1));
}

// ---------------- pack W_hh into per-feature B-fragment layout (tf32) ----------------
// P[i][ ((w*6 + nt)*16 + kt)*64 + lane*2 + c ]
//   = tf32( W_hh[i][ gate*128 + j ][ k ] )
// gate = nt>>1 ; j = 16*w + 8*(nt&1) + (lane>>2) ; k = 8*kt + (lane&3) + 4*c
__global__ void pack_whh_kernel(const float* __restrict__ W_hh, float* __restrict__ P)
{
    int idx = blockIdx.x * blockDim.x + threadIdx.x;
    if (idx >= I_SZ * G_SZ * H_SZ) return;
    int i  = idx / 49152;
    int r  = idx % 49152;
    int w  = r / 6144;  r %= 6144;
    int nt = r / 1024;  r %= 1024;
    int kt = r / 64;    r %= 64;
    int lane = r >> 1;
    int c = r & 1;
    int gate = nt >> 1;
    int j = 16 * w + 8 * (nt & 1) + (lane >> 2);
    int k = 8 * kt + (lane & 3) + 4 * c;
    float v = W_hh[((size_t)i * G_SZ + gate * 128 + j) * H_SZ + k];
    ((uint32_t*)P)[idx] = tf32_bits(v);
}

// ---------------- transpose the 7 [H,H] weight matrices ----------------
__global__ void transpose7_kernel(const float* __restrict__ fp, const float* __restrict__ g1,
                                  const float* __restrict__ g2, const float* __restrict__ wk,
                                  const float* __restrict__ wv, const float* __restrict__ wq,
                                  const float* __restrict__ o0, float* __restrict__ out)
{
    int idx = blockIdx.x * blockDim.x + threadIdx.x;
    if (idx >= 7 * H_SZ * H_SZ) return;
    int w = idx >> 14;
    int r = idx & 16383;
    int k = r >> 7, n = r & 127;
    const float* src = (w == 0) ? fp : (w == 1) ? g1 : (w == 2) ? g2 :
                       (w == 3) ? wk : (w == 4) ? wv : (w == 5) ? wq : o0;
    out[idx] = src[n * 128 + k];
}

// ---------------- GRU scan via mma.sync tf32 ----------------
// grid = (8 batch-blocks, 64 features), 256 threads (8 warps)
// warp w owns N-slice: gate-cols for j in [16w, 16w+16), all three gates,
// over all M=64 batch rows (4 m-tiles of 16).
#define SMEM_B_BYTES   196608               // W image
#define SMEM_H_OFF     196608               // h fragment tile
#define SMEM_H_BYTES   32768                // 16 kt * 4 mt * 32 lanes * 16B
#define SMEM_TOT       (SMEM_B_BYTES + SMEM_H_BYTES)

__global__ __launch_bounds__(256, 1) void gru_kernel(
    const float* __restrict__ x,      // [B][T][I]
    const float* __restrict__ P,      // packed W (fragment layout, tf32 bits)
    const float* __restrict__ W_ih,   // [I][3H]
    const float* __restrict__ b_ih,
    const float* __restrict__ b_hh,
    float* __restrict__ hs_out)       // [B][I][H]
{
    extern __shared__ char smem[];
    float*  s_B = (float*)smem;
    char*   s_H = smem + SMEM_H_OFF;

    const int i   = blockIdx.y;
    const int b0  = blockIdx.x * 64;
    const int tid = threadIdx.x;
    const int w   = tid >> 5;
    const int lane = tid & 31;
    const int g   = lane >> 2;        // group id (row within tile)
    const int t4  = lane & 3;

    // ---- stage W image into smem (once) ----
    {
        const float4* src = (const float4*)(P + (size_t)i * (G_SZ * H_SZ));
        float4* dst = (float4*)s_B;
        for (int idx = tid; idx < (G_SZ * H_SZ) / 4; idx += 256) dst[idx] = src[idx];
    }

    // ---- per-thread gate constants (4 j-values) ----
    float wr[4], wz[4], wn[4], ccr[4], ccz[4], bin[4], bhn[4];
#pragma unroll
    for (int p = 0; p < 4; p++) {
        const int j = 16 * w + 8 * (p >> 1) + 2 * t4 + (p & 1);
        const int base = i * G_SZ + j;
        wr[p]  = __ldg(&W_ih[base]);
        wz[p]  = __ldg(&W_ih[base + 128]);
        wn[p]  = __ldg(&W_ih[base + 256]);
        ccr[p] = __ldg(&b_ih[base])       + __ldg(&b_hh[base]);
        ccz[p] = __ldg(&b_ih[base + 128]) + __ldg(&b_hh[base + 128]);
        bin[p] = __ldg(&b_ih[base + 256]);
        bhn[p] = __ldg(&b_hh[base + 256]);
    }

    // x pointers for this thread's 8 batch rows
    const float* xptr[4][2];
#pragma unroll
    for (int mt = 0; mt < 4; mt++)
#pragma unroll
        for (int hi = 0; hi < 2; hi++)
            xptr[mt][hi] = x + (size_t)(b0 + 16 * mt + g + 8 * hi) * (T_SZ * I_SZ) + i;

    // h state registers: h[b = 16mt + g + 8hi][j(p)]
    float hcur[4][4][2];
#pragma unroll
    for (int mt = 0; mt < 4; mt++)
#pragma unroll
        for (int p = 0; p < 4; p++)
            hcur[mt][p][0] = hcur[mt][p][1] = 0.0f;

    __syncthreads();   // W image ready

    const float2* bf = (const float2*)s_B;
    const float4* hf = (const float4*)s_H;
    const int bofs = w * 96 * 32 + lane;   // float2 index base for this warp

    const float NL2E = -1.4426950408889634f;

    for (int t = 0; t < T_SZ; t++) {
        // ---- write h_t into fragment tile ----
        if (t > 0) {
#pragma unroll
            for (int p = 0; p < 4; p++) {
                const int kk = 2 * t4 + (p & 1);
                const int kt = 2 * w + (p >> 1);
#pragma unroll
                for (int mt = 0; mt < 4; mt++) {
                    const int cell = (kt * 4 + mt) * 32 + g * 4 + (kk & 3);
                    float2 v;
                    v.x = __uint_as_float(tf32_bits(hcur[mt][p][0]));
                    v.y = __uint_as_float(tf32_bits(hcur[mt][p][1]));
                    *(float2*)(s_H + cell * 16 + (kk >> 2) * 8) = v;
                }
            }
        }
        __syncthreads();

        // ---- GEMM: D[4 mt][6 nt][4] += h @ W^T ----
        float D[4][6][4];
#pragma unroll
        for (int mt = 0; mt < 4; mt++)
#pragma unroll
            for (int nt = 0; nt < 6; nt++)
#pragma unroll
                for (int c = 0; c < 4; c++) D[mt][nt][c] = 0.0f;

        if (t > 0) {
#pragma unroll 2
            for (int kt = 0; kt < 16; kt++) {
                uint32_t a[4][4];
#pragma unroll
                for (int mt = 0; mt < 4; mt++) {
                    float4 av = hf[(kt * 4 + mt) * 32 + lane];
                    a[mt][0] = __float_as_uint(av.x);
                    a[mt][1] = __float_as_uint(av.y);
                    a[mt][2] = __float_as_uint(av.z);
                    a[mt][3] = __float_as_uint(av.w);
                }
#pragma unroll
                for (int nt = 0; nt < 6; nt++) {
                    float2 bv = bf[bofs + (nt * 16 + kt) * 32];
                    const uint32_t bb0 = __float_as_uint(bv.x);
                    const uint32_t bb1 = __float_as_uint(bv.y);
#pragma unroll
                    for (int mt = 0; mt < 4; mt++)
                        mma_tf32(D[mt][nt], a[mt], bb0, bb1);
                }
            }
        }
        __syncthreads();   // all reads done before next step's writes

        // ---- epilogue: gates + state update ----
        float xv[4][2];
#pragma unroll
        for (int mt = 0; mt < 4; mt++)
#pragma unroll
            for (int hi = 0; hi < 2; hi++)
                xv[mt][hi] = __ldg(xptr[mt][hi] + t * I_SZ);

#pragma unroll
        for (int mt = 0; mt < 4; mt++) {
#pragma unroll
            for (int p = 0; p < 4; p++) {
                const int nA = p >> 1, dj = p & 1;
#pragma unroll
                for (int hi = 0; hi < 2; hi++) {
                    const int c = hi * 2 + dj;
                    const float xt = xv[mt][hi];
                    const float ur = fmaf(xt, wr[p], ccr[p]) + D[mt][nA][c];
                    const float uz = fmaf(xt, wz[p], ccz[p]) + D[mt][2 + nA][c];
                    const float er = exp2f(NL2E * ur);
                    const float ez = exp2f(NL2E * uz);
                    const float r  = __fdividef(1.0f, 1.0f + er);
                    const float z  = __fdividef(1.0f, 1.0f + ez);
                    const float inn = fmaf(xt, wn[p], bin[p]);
                    const float hn  = D[mt][4 + nA][c] + bhn[p];
                    const float arg = fmaf(r, hn, inn);
                    const float e2  = exp2f(2.0f * NL2E * arg);
                    const float th  = (1.0f - e2) * __fdividef(1.0f, 1.0f + e2);
                    hcur[mt][p][hi] = fmaf(z, hcur[mt][p][hi] - th, th);
                }
            }
        }
    }

    // ---- write final hidden state: hs[b][i][j] ----
#pragma unroll
    for (int mt = 0; mt < 4; mt++)
#pragma unroll
        for (int p = 0; p < 4; p++) {
            const int j = 16 * w + 8 * (p >> 1) + 2 * t4 + (p & 1);
#pragma unroll
            for (int hi = 0; hi < 2; hi++) {
                const int b = b0 + 16 * mt + g + 8 * hi;
                hs_out[((size_t)b * I_SZ + i) * H_SZ + j] = hcur[mt][p][hi];
            }
        }
}

// ---------------- generic linear ----------------
__global__ __launch_bounds__(256) void lin_kernel(
    const float* __restrict__ X, const float* __restrict__ Wt,
    const float* __restrict__ bias, float* __restrict__ Y, int relu)
{
    __shared__ float Xs[64][128];
    const int m0 = blockIdx.x * 64;
    const int tid = threadIdx.x, w = tid >> 5, l = tid & 31;
    for (int idx = tid; idx < 64 * 128; idx += 256)
        Xs[idx >> 7][idx & 127] = X[(size_t)m0 * 128 + idx];
    __syncthreads();

    float acc[8][4];
#pragma unroll
    for (int rr = 0; rr < 8; rr++)
#pragma unroll
        for (int c = 0; c < 4; c++) acc[rr][c] = 0.f;

    const int r0 = w * 8;
#pragma unroll 4
    for (int k = 0; k < 128; k++) {
        float wv[4];
#pragma unroll
        for (int c = 0; c < 4; c++) wv[c] = __ldg(&Wt[k * 128 + l + 32 * c]);
#pragma unroll
        for (int rr = 0; rr < 8; rr++) {
            const float xv = Xs[r0 + rr][k];
#pragma unroll
            for (int c = 0; c < 4; c++) acc[rr][c] = fmaf(xv, wv[c], acc[rr][c]);
        }
    }
#pragma unroll
    for (int rr = 0; rr < 8; rr++)
#pragma unroll
        for (int c = 0; c < 4; c++) {
            const int n = l + 32 * c;
            float v = acc[rr][c] + __ldg(&bias[n]);
            if (relu) v = fmaxf(v, 0.f);
            Y[(size_t)(m0 + r0 + rr) * 128 + n] = v;
        }
}

// ---------------- adjacency conv ----------------
__global__ __launch_bounds__(256) void adjmul_kernel(
    const float* __restrict__ X, const float* __restrict__ adj, float* __restrict__ Y)
{
    __shared__ float Xs[64][128];
    const int b = blockIdx.x;
    const int tid = threadIdx.x, w = tid >> 5, l = tid & 31;
    for (int idx = tid; idx < 64 * 128; idx += 256)
        Xs[idx >> 7][idx & 127] = X[(size_t)b * 8192 + idx];
    __syncthreads();

    float acc[8][4];
#pragma unroll
    for (int ii = 0; ii < 8; ii++)
#pragma unroll
        for (int c = 0; c < 4; c++) acc[ii][c] = 0.f;

    const int i0 = w * 8;
#pragma unroll 4
    for (int j = 0; j < 64; j++) {
        float hv[4];
#pragma unroll
        for (int c = 0; c < 4; c++) hv[c] = Xs[j][l + 32 * c];
#pragma unroll
        for (int ii = 0; ii < 8; ii++) {
            const float a = __ldg(&adj[(i0 + ii) * 64 + j]);
#pragma unroll
            for (int c = 0; c < 4; c++) acc[ii][c] = fmaf(a, hv[c], acc[ii][c]);
        }
    }
#pragma unroll
    for (int ii = 0; ii < 8; ii++)
#pragma unroll
        for (int c = 0; c < 4; c++)
            Y[(size_t)b * 8192 + (i0 + ii) * 128 + l + 32 * c] = acc[ii][c];
}

// ---------------- attention + output head ----------------
__global__ __launch_bounds__(128) void attn_kernel(
    const float* __restrict__ ctx, const float* __restrict__ K, const float* __restrict__ V,
    const float* __restrict__ wqT, const float* __restrict__ wq_b,
    const float* __restrict__ o0T, const float* __restrict__ o0_b,
    float* __restrict__ out)
{
    __shared__ float ctxl[128], qv[128], ev[64], red[2], wc[128];
    const int b = blockIdx.x, t = threadIdx.x;

    ctxl[t] = ctx[(size_t)b * 8192 + 63 * 128 + t];
    __syncthreads();

    float s = __ldg(&wq_b[t]);
    for (int k = 0; k < 128; k++) s = fmaf(ctxl[k], __ldg(&wqT[k * 128 + t]), s);
    qv[t] = s;
    __syncthreads();

    if (t < 64) {
        float e = 0.f;
        const float* Kp = K + (size_t)b * 8192 + t * 128;
        for (int h = 0; h < 128; h++) e = fmaf(Kp[h], qv[h], e);
        ev[t] = e;
    }
    __syncthreads();
    if (t == 0) {
        float mx = -1e30f;
        for (int ii = 0; ii < 64; ii++) mx = fmaxf(mx, ev[ii]);
        float sm = 0.f;
        for (int ii = 0; ii < 64; ii++) sm += __expf(ev[ii] - mx);
        red[0] = mx; red[1] = 1.0f / sm;
    }
    __syncthreads();
    if (t < 64) ev[t] = __expf(ev[t] - red[0]) * red[1];
    __syncthreads();

    float acc = 0.f;
    for (int ii = 0; ii < 64; ii++)
        acc = fmaf(ev[ii], V[(size_t)b * 8192 + ii * 128 + t], acc);
    wc[t] = acc;
    __syncthreads();

    float o = __ldg(&o0_b[t]);
    for (int h = 0; h < 128; h++) o = fmaf(wc[h], __ldg(&o0T[h * 128 + t]), o);
    out[(size_t)b * 128 + t] = fmaxf(o, 0.f);
}

// ---------------- launch ----------------
extern "C" void kernel_launch(void* const* d_in, const int* in_sizes, int n_in,
                              void* d_out, int out_size)
{
    const float* x     = (const float*)d_in[0];
    const float* W_ih  = (const float*)d_in[1];
    const float* W_hh  = (const float*)d_in[2];
    const float* b_ih  = (const float*)d_in[3];
    const float* b_hh  = (const float*)d_in[4];
    const float* fp_w  = (const float*)d_in[5];
    const float* fp_b  = (const float*)d_in[6];
    const float* g1_w  = (const float*)d_in[7];
    const float* g1_b  = (const float*)d_in[8];
    const float* g2_w  = (const float*)d_in[9];
    const float* g2_b  = (const float*)d_in[10];
    const float* wq_w  = (const float*)d_in[11];
    const float* wq_b  = (const float*)d_in[12];
    const float* wk_w  = (const float*)d_in[13];
    const float* wk_b  = (const float*)d_in[14];
    const float* wv_w  = (const float*)d_in[15];
    const float* wv_b  = (const float*)d_in[16];
    const float* o0_w  = (const float*)d_in[17];
    const float* o0_b  = (const float*)d_in[18];
    const float* adj   = (const float*)d_in[19];

    float* out = (float*)d_out;
    float* ht_out = out + B_SZ * H_SZ;

    float *P, *hs, *A, *Bf, *Wt;
    cudaGetSymbolAddress((void**)&P,  g_P);
    cudaGetSymbolAddress((void**)&hs, g_hs);
    cudaGetSymbolAddress((void**)&A,  g_A);
    cudaGetSymbolAddress((void**)&Bf, g_B);
    cudaGetSymbolAddress((void**)&Wt, g_Wt);

    static int smem_set = 0;
    if (!smem_set) {
        cudaFuncSetAttribute(gru_kernel, cudaFuncAttributeMaxDynamicSharedMemorySize, SMEM_TOT);
        smem_set = 1;
    }

    {
        int n = I_SZ * G_SZ * H_SZ;
        pack_whh_kernel<<<(n + 255) / 256, 256>>>(W_hh, P);
    }
    {
        int n = 7 * H_SZ * H_SZ;
        transpose7_kernel<<<(n + 255) / 256, 256>>>(fp_w, g1_w, g2_w, wk_w, wv_w, wq_w, o0_w, Wt);
    }

    const float* fpT = Wt + 0 * 16384;
    const float* g1T = Wt + 1 * 16384;
    const float* g2T = Wt + 2 * 16384;
    const float* wkT = Wt + 3 * 16384;
    const float* wvT = Wt + 4 * 16384;
    const float* wqT = Wt + 5 * 16384;
    const float* o0T = Wt + 6 * 16384;

    // 1) GRU scan -> hs (mma.sync tf32)
    gru_kernel<<<dim3(8, 64), 256, SMEM_TOT>>>(x, P, W_ih, b_ih, b_hh, hs);

    const int M = B_SZ * I_SZ;
    // 2) ht
    lin_kernel<<<M / 64, 256>>>(hs, fpT, fp_b, ht_out, 0);
    // 3) g
    adjmul_kernel<<<B_SZ, 256>>>(ht_out, adj, A);
    lin_kernel<<<M / 64, 256>>>(A, g1T, g1_b, Bf, 1);
    // 4) ctx
    adjmul_kernel<<<B_SZ, 256>>>(Bf, adj, A);
    lin_kernel<<<M / 64, 256>>>(A, g2T, g2_b, Bf, 1);
    // 5) K, V
    lin_kernel<<<M / 64, 256>>>(Bf, wkT, wk_b, A, 0);
    lin_kernel<<<M / 64, 256>>>(Bf, wvT, wv_b, hs, 0);
    // 6) attention + head
    attn_kernel<<<B_SZ, 128>>>(Bf, A, hs, wqT, wq_b, o0T, o0_b, out);
}

// round 6
// speedup vs baseline: 7.3599x; 1.6942x over previous
#include <cuda_runtime.h>
#include <cuda_bf16.h>
#include <cuda_fp16.h>
#include <math.h>
#include <stdint.h>

// Problem constants
#define B_SZ 512
#define T_SZ 64
#define I_SZ 64
#define H_SZ 128
#define G_SZ 384   // 3*H

// ---------------- device scratch (no allocations allowed) ----------------
__device__ uint32_t g_P [I_SZ * 24576];             // per-feature W_hh, fp16 B-fragment layout (6MB)
__device__ float g_hs[B_SZ * I_SZ * H_SZ];          // GRU final hidden / later V
__device__ float g_A [B_SZ * I_SZ * H_SZ];          // xT during GRU, then ctx / scratch
__device__ float g_B [B_SZ * I_SZ * H_SZ];          // scratch (g, then K)
__device__ float g_Wt[7 * H_SZ * H_SZ];             // transposed tail weights

__device__ __forceinline__ void mma_f16(float* d, const uint32_t* a, uint32_t b0, uint32_t b1) {
    asm volatile(
        "mma.sync.aligned.m16n8k16.row.col.f32.f16.f16.f32 "
        "{%0,%1,%2,%3}, {%4,%5,%6,%7}, {%8,%9}, {%0,%1,%2,%3};"
        : "+f"(d[0]), "+f"(d[1]), "+f"(d[2]), "+f"(d[3])
        : "r"(a[0]), "r"(a[1]), "r"(a[2]), "r"(a[3]), "r"(b0), "r"(b1));
}

// ---------------- pack W_hh into per-feature fp16 B-fragment layout ----------------
// P[i][ ((w*6+nt)*8+kt)*64 + lane*2 + reg ] = half2( W[gate*128+j][k0], W[...][k0+1] )
// gate=nt>>1 ; j=16w+8(nt&1)+(lane>>2) ; k0=16kt+8reg+2(lane&3)
__global__ void pack_whh_kernel(const float* __restrict__ W_hh, uint32_t* __restrict__ P)
{
    int idx = blockIdx.x * blockDim.x + threadIdx.x;
    if (idx >= I_SZ * 24576) return;
    int i = idx / 24576;
    int r = idx % 24576;
    int w  = r / 3072; r %= 3072;
    int nt = r / 512;  r %= 512;
    int kt = r / 64;   r %= 64;
    int lane = r >> 1;
    int reg  = r & 1;
    int g  = lane >> 2, t4 = lane & 3;
    int k0 = 16 * kt + 8 * reg + 2 * t4;
    int j  = 16 * w + 8 * (nt & 1) + g;
    int gate = nt >> 1;
    const float* src = W_hh + ((size_t)i * G_SZ + gate * 128 + j) * H_SZ + k0;
    __half2 h2 = __floats2half2_rn(src[0], src[1]);
    P[idx] = *reinterpret_cast<uint32_t*>(&h2);
}

// ---------------- transpose x: xT[t][i][b] = x[b][t][i] ----------------
__global__ void xt_kernel(const float* __restrict__ x, float* __restrict__ xT)
{
    int idx = blockIdx.x * blockDim.x + threadIdx.x;
    if (idx >= B_SZ * T_SZ * I_SZ) return;
    int b = idx & 511;
    int r = idx >> 9;
    int i = r & 63;
    int t = r >> 6;
    xT[idx] = x[((size_t)b * T_SZ + t) * I_SZ + i];
}

// ---------------- transpose the 7 [H,H] weight matrices ----------------
__global__ void transpose7_kernel(const float* __restrict__ fp, const float* __restrict__ g1,
                                  const float* __restrict__ g2, const float* __restrict__ wk,
                                  const float* __restrict__ wv, const float* __restrict__ wq,
                                  const float* __restrict__ o0, float* __restrict__ out)
{
    int idx = blockIdx.x * blockDim.x + threadIdx.x;
    if (idx >= 7 * H_SZ * H_SZ) return;
    int w = idx >> 14;
    int r = idx & 16383;
    int k = r >> 7, n = r & 127;
    const float* src = (w == 0) ? fp : (w == 1) ? g1 : (w == 2) ? g2 :
                       (w == 3) ? wk : (w == 4) ? wv : (w == 5) ? wq : o0;
    out[idx] = src[n * 128 + k];
}

// ---------------- GRU scan via mma.sync fp16 (fp32 accum) ----------------
// grid = (16 batch-blocks of 32, 64 features), 256 threads (8 warps)
// warp w owns N-slice j in [16w, 16w+16) x 3 gates, M=32 (2 m-tiles of 16), K=128 (8 kt of 16)
#define GRU_SMEM_W 98304                     // 24576 uint32
#define GRU_SMEM   (GRU_SMEM_W + 8192)       // + A fragment tile (8 kt * 2 mt * 32 * 16B)

__global__ __launch_bounds__(256, 2) void gru_kernel(
    const float* __restrict__ xT,     // [T][I][B]
    const uint32_t* __restrict__ P,   // packed W (fp16 fragment layout)
    const float* __restrict__ W_ih,   // [I][3H]
    const float* __restrict__ b_ih,
    const float* __restrict__ b_hh,
    float* __restrict__ hs_out)       // [B][I][H]
{
    extern __shared__ char smem[];
    uint32_t* s_B = (uint32_t*)smem;
    uint4*    s_A = (uint4*)(smem + GRU_SMEM_W);

    const int i   = blockIdx.y;
    const int b0  = blockIdx.x * 32;
    const int tid = threadIdx.x;
    const int w    = tid >> 5;
    const int lane = tid & 31;
    const int g    = lane >> 2;
    const int t4   = lane & 3;

    // ---- stage W image (96KB) ----
    {
        const uint4* src = (const uint4*)(P + (size_t)i * 24576);
        uint4* dst = (uint4*)s_B;
        for (int idx = tid; idx < 6144; idx += 256) dst[idx] = src[idx];
    }

    // ---- per-thread gate constants (4 j-values) ----
    float wr[4], wz[4], wn[4], ccr[4], ccz[4], bin[4], bhn[4];
#pragma unroll
    for (int p = 0; p < 4; p++) {
        const int j = 16 * w + 8 * (p >> 1) + 2 * t4 + (p & 1);
        const int base = i * G_SZ + j;
        wr[p]  = __ldg(&W_ih[base]);
        wz[p]  = __ldg(&W_ih[base + 128]);
        wn[p]  = __ldg(&W_ih[base + 256]);
        ccr[p] = __ldg(&b_ih[base])       + __ldg(&b_hh[base]);
        ccz[p] = __ldg(&b_ih[base + 128]) + __ldg(&b_hh[base + 128]);
        bin[p] = __ldg(&b_ih[base + 256]);
        bhn[p] = __ldg(&b_hh[base + 256]);
    }

    // h state: h[b = 16mt + g + 8hi][j(p)]
    float hcur[2][4][2];
#pragma unroll
    for (int mt = 0; mt < 2; mt++)
#pragma unroll
        for (int p = 0; p < 4; p++)
            hcur[mt][p][0] = hcur[mt][p][1] = 0.0f;

    __syncthreads();

    const float NL2E = -1.4426950408889634f;
    const float* xrow = xT + (size_t)i * B_SZ + b0;   // advances by I*B stride each step

    for (int t = 0; t < T_SZ; t++) {
        // ---- pack h_t into A-fragment tile (thread writes its own fragment, kt = w) ----
        if (t > 0) {
#pragma unroll
            for (int mt = 0; mt < 2; mt++) {
                uint32_t rr[4];
#pragma unroll
                for (int q = 0; q < 2; q++)
#pragma unroll
                    for (int hi = 0; hi < 2; hi++) {
                        __half2 h2 = __floats2half2_rn(hcur[mt][2 * q][hi], hcur[mt][2 * q + 1][hi]);
                        rr[2 * q + hi] = *reinterpret_cast<uint32_t*>(&h2);
                    }
                s_A[(w * 2 + mt) * 32 + lane] = make_uint4(rr[0], rr[1], rr[2], rr[3]);
            }
        }
        __syncthreads();

        // ---- GEMM: D[2 mt][6 nt][4] += h @ W^T ----
        float D[2][6][4];
#pragma unroll
        for (int mt = 0; mt < 2; mt++)
#pragma unroll
            for (int nt = 0; nt < 6; nt++)
#pragma unroll
                for (int c = 0; c < 4; c++) D[mt][nt][c] = 0.0f;

        if (t > 0) {
#pragma unroll
            for (int kt = 0; kt < 8; kt++) {
                uint4 a0 = s_A[(kt * 2 + 0) * 32 + lane];
                uint4 a1 = s_A[(kt * 2 + 1) * 32 + lane];
                uint32_t af0[4] = {a0.x, a0.y, a0.z, a0.w};
                uint32_t af1[4] = {a1.x, a1.y, a1.z, a1.w};
#pragma unroll
                for (int nt = 0; nt < 6; nt++) {
                    uint2 bv = *(const uint2*)(s_B + ((w * 6 + nt) * 8 + kt) * 64 + lane * 2);
                    mma_f16(D[0][nt], af0, bv.x, bv.y);
                    mma_f16(D[1][nt], af1, bv.x, bv.y);
                }
            }
        }
        __syncthreads();

        // ---- coalesced x loads (1 sector each, L1-resident) ----
        float xv[2][2];
#pragma unroll
        for (int mt = 0; mt < 2; mt++)
#pragma unroll
            for (int hi = 0; hi < 2; hi++)
                xv[mt][hi] = __ldg(xrow + 16 * mt + g + 8 * hi);
        xrow += I_SZ * B_SZ;

        // ---- epilogue: gates + state update ----
#pragma unroll
        for (int mt = 0; mt < 2; mt++) {
#pragma unroll
            for (int p = 0; p < 4; p++) {
                const int nA = p >> 1, dj = p & 1;
#pragma unroll
                for (int hi = 0; hi < 2; hi++) {
                    const int c = hi * 2 + dj;
                    const float xt = xv[mt][hi];
                    const float ur = fmaf(xt, wr[p], ccr[p]) + D[mt][nA][c];
                    const float uz = fmaf(xt, wz[p], ccz[p]) + D[mt][2 + nA][c];
                    const float er = exp2f(NL2E * ur);
                    const float ez = exp2f(NL2E * uz);
                    const float r  = __fdividef(1.0f, 1.0f + er);
                    const float z  = __fdividef(1.0f, 1.0f + ez);
                    const float inn = fmaf(xt, wn[p], bin[p]);
                    const float hn  = D[mt][4 + nA][c] + bhn[p];
                    const float arg = fmaf(r, hn, inn);
                    const float e2  = exp2f(2.0f * NL2E * arg);
                    const float th  = (1.0f - e2) * __fdividef(1.0f, 1.0f + e2);
                    hcur[mt][p][hi] = fmaf(z, hcur[mt][p][hi] - th, th);
                }
            }
        }
    }

    // ---- write final hidden state ----
#pragma unroll
    for (int mt = 0; mt < 2; mt++)
#pragma unroll
        for (int p = 0; p < 4; p++) {
            const int j = 16 * w + 8 * (p >> 1) + 2 * t4 + (p & 1);
#pragma unroll
            for (int hi = 0; hi < 2; hi++) {
                const int b = b0 + 16 * mt + g + 8 * hi;
                hs_out[((size_t)b * I_SZ + i) * H_SZ + j] = hcur[mt][p][hi];
            }
        }
}

// ---------------- generic linear: Y = X @ Wt + b ----------------
__global__ __launch_bounds__(256) void lin_kernel(
    const float* __restrict__ X, const float* __restrict__ Wt,
    const float* __restrict__ bias, float* __restrict__ Y, int relu)
{
    __shared__ float Xs[64][128];
    const int m0 = blockIdx.x * 64;
    const int tid = threadIdx.x, w = tid >> 5, l = tid & 31;
    for (int idx = tid; idx < 64 * 128; idx += 256)
        Xs[idx >> 7][idx & 127] = X[(size_t)m0 * 128 + idx];
    __syncthreads();

    float acc[8][4];
#pragma unroll
    for (int rr = 0; rr < 8; rr++)
#pragma unroll
        for (int c = 0; c < 4; c++) acc[rr][c] = 0.f;

    const int r0 = w * 8;
#pragma unroll 4
    for (int k = 0; k < 128; k++) {
        float wv[4];
#pragma unroll
        for (int c = 0; c < 4; c++) wv[c] = __ldg(&Wt[k * 128 + l + 32 * c]);
#pragma unroll
        for (int rr = 0; rr < 8; rr++) {
            const float xv = Xs[r0 + rr][k];
#pragma unroll
            for (int c = 0; c < 4; c++) acc[rr][c] = fmaf(xv, wv[c], acc[rr][c]);
        }
    }
#pragma unroll
    for (int rr = 0; rr < 8; rr++)
#pragma unroll
        for (int c = 0; c < 4; c++) {
            const int n = l + 32 * c;
            float v = acc[rr][c] + __ldg(&bias[n]);
            if (relu) v = fmaxf(v, 0.f);
            Y[(size_t)(m0 + r0 + rr) * 128 + n] = v;
        }
}

// ---------------- fused: Y = relu((adj @ X) @ Wt + b), one block per batch ----------------
__global__ __launch_bounds__(256) void adjlin_kernel(
    const float* __restrict__ X, const float* __restrict__ adj,
    const float* __restrict__ Wt, const float* __restrict__ bias,
    float* __restrict__ Y)
{
    extern __shared__ float sm[];
    float* Xs = sm;           // [64][128]
    float* Zs = sm + 8192;    // [64][128]
    const int b = blockIdx.x;
    const int tid = threadIdx.x, w = tid >> 5, l = tid & 31;
    const int r0 = w * 8;

    for (int idx = tid; idx < 8192; idx += 256)
        Xs[idx] = X[(size_t)b * 8192 + idx];
    __syncthreads();

    // Z = adj @ X
    {
        float acc[8][4];
#pragma unroll
        for (int ii = 0; ii < 8; ii++)
#pragma unroll
            for (int c = 0; c < 4; c++) acc[ii][c] = 0.f;
#pragma unroll 4
        for (int j = 0; j < 64; j++) {
            float hv[4];
#pragma unroll
            for (int c = 0; c < 4; c++) hv[c] = Xs[j * 128 + l + 32 * c];
#pragma unroll
            for (int ii = 0; ii < 8; ii++) {
                const float a = __ldg(&adj[(r0 + ii) * 64 + j]);
#pragma unroll
                for (int c = 0; c < 4; c++) acc[ii][c] = fmaf(a, hv[c], acc[ii][c]);
            }
        }
#pragma unroll
        for (int ii = 0; ii < 8; ii++)
#pragma unroll
            for (int c = 0; c < 4; c++)
                Zs[(r0 + ii) * 128 + l + 32 * c] = acc[ii][c];
    }
    __syncthreads();

    // Y = relu(Z @ Wt + b)
    {
        float acc[8][4];
#pragma unroll
        for (int rr = 0; rr < 8; rr++)
#pragma unroll
            for (int c = 0; c < 4; c++) acc[rr][c] = 0.f;
#pragma unroll 4
        for (int k = 0; k < 128; k++) {
            float wv[4];
#pragma unroll
            for (int c = 0; c < 4; c++) wv[c] = __ldg(&Wt[k * 128 + l + 32 * c]);
#pragma unroll
            for (int rr = 0; rr < 8; rr++) {
                const float xv = Zs[(r0 + rr) * 128 + k];
#pragma unroll
                for (int c = 0; c < 4; c++) acc[rr][c] = fmaf(xv, wv[c], acc[rr][c]);
            }
        }
#pragma unroll
        for (int rr = 0; rr < 8; rr++)
#pragma unroll
            for (int c = 0; c < 4; c++) {
                const int n = l + 32 * c;
                Y[(size_t)b * 8192 + (r0 + rr) * 128 + n] = fmaxf(acc[rr][c] + __ldg(&bias[n]), 0.f);
            }
    }
}

// ---------------- fused K,V: one ctx load, two linears ----------------
__global__ __launch_bounds__(256) void kv_kernel(
    const float* __restrict__ ctx,
    const float* __restrict__ wkT, const float* __restrict__ wk_b,
    const float* __restrict__ wvT, const float* __restrict__ wv_b,
    float* __restrict__ K, float* __restrict__ V)
{
    __shared__ float Xs[64][128];
    const int b = blockIdx.x;
    const int tid = threadIdx.x, w = tid >> 5, l = tid & 31;
    const int r0 = w * 8;

    for (int idx = tid; idx < 8192; idx += 256)
        Xs[idx >> 7][idx & 127] = ctx[(size_t)b * 8192 + idx];
    __syncthreads();

#pragma unroll
    for (int pass = 0; pass < 2; pass++) {
        const float* Wt = pass ? wvT : wkT;
        const float* bias = pass ? wv_b : wk_b;
        float* Y = pass ? V : K;
        float acc[8][4];
#pragma unroll
        for (int rr = 0; rr < 8; rr++)
#pragma unroll
            for (int c = 0; c < 4; c++) acc[rr][c] = 0.f;
#pragma unroll 4
        for (int k = 0; k < 128; k++) {
            float wv[4];
#pragma unroll
            for (int c = 0; c < 4; c++) wv[c] = __ldg(&Wt[k * 128 + l + 32 * c]);
#pragma unroll
            for (int rr = 0; rr < 8; rr++) {
                const float xv = Xs[r0 + rr][k];
#pragma unroll
                for (int c = 0; c < 4; c++) acc[rr][c] = fmaf(xv, wv[c], acc[rr][c]);
            }
        }
#pragma unroll
        for (int rr = 0; rr < 8; rr++)
#pragma unroll
            for (int c = 0; c < 4; c++) {
                const int n = l + 32 * c;
                Y[(size_t)b * 8192 + (r0 + rr) * 128 + n] = acc[rr][c] + __ldg(&bias[n]);
            }
    }
}

// ---------------- attention + output head ----------------
__global__ __launch_bounds__(128) void attn_kernel(
    const float* __restrict__ ctx, const float* __restrict__ K, const float* __restrict__ V,
    const float* __restrict__ wqT, const float* __restrict__ wq_b,
    const float* __restrict__ o0T, const float* __restrict__ o0_b,
    float* __restrict__ out)
{
    __shared__ float ctxl[128], qv[128], ev[64], red[2], wc[128];
    const int b = blockIdx.x, t = threadIdx.x;

    ctxl[t] = ctx[(size_t)b * 8192 + 63 * 128 + t];
    __syncthreads();

    float s = __ldg(&wq_b[t]);
    for (int k = 0; k < 128; k++) s = fmaf(ctxl[k], __ldg(&wqT[k * 128 + t]), s);
    qv[t] = s;
    __syncthreads();

    if (t < 64) {
        float e = 0.f;
        const float* Kp = K + (size_t)b * 8192 + t * 128;
        for (int h = 0; h < 128; h++) e = fmaf(Kp[h], qv[h], e);
        ev[t] = e;
    }
    __syncthreads();
    if (t == 0) {
        float mx = -1e30f;
        for (int ii = 0; ii < 64; ii++) mx = fmaxf(mx, ev[ii]);
        float sm = 0.f;
        for (int ii = 0; ii < 64; ii++) sm += __expf(ev[ii] - mx);
        red[0] = mx; red[1] = 1.0f / sm;
    }
    __syncthreads();
    if (t < 64) ev[t] = __expf(ev[t] - red[0]) * red[1];
    __syncthreads();

    float acc = 0.f;
    for (int ii = 0; ii < 64; ii++)
        acc = fmaf(ev[ii], V[(size_t)b * 8192 + ii * 128 + t], acc);
    wc[t] = acc;
    __syncthreads();

    float o = __ldg(&o0_b[t]);
    for (int h = 0; h < 128; h++) o = fmaf(wc[h], __ldg(&o0T[h * 128 + t]), o);
    out[(size_t)b * 128 + t] = fmaxf(o, 0.f);
}

// ---------------- launch ----------------
extern "C" void kernel_launch(void* const* d_in, const int* in_sizes, int n_in,
                              void* d_out, int out_size)
{
    const float* x     = (const float*)d_in[0];
    const float* W_ih  = (const float*)d_in[1];
    const float* W_hh  = (const float*)d_in[2];
    const float* b_ih  = (const float*)d_in[3];
    const float* b_hh  = (const float*)d_in[4];
    const float* fp_w  = (const float*)d_in[5];
    const float* fp_b  = (const float*)d_in[6];
    const float* g1_w  = (const float*)d_in[7];
    const float* g1_b  = (const float*)d_in[8];
    const float* g2_w  = (const float*)d_in[9];
    const float* g2_b  = (const float*)d_in[10];
    const float* wq_w  = (const float*)d_in[11];
    const float* wq_b  = (const float*)d_in[12];
    const float* wk_w  = (const float*)d_in[13];
    const float* wk_b  = (const float*)d_in[14];
    const float* wv_w  = (const float*)d_in[15];
    const float* wv_b  = (const float*)d_in[16];
    const float* o0_w  = (const float*)d_in[17];
    const float* o0_b  = (const float*)d_in[18];
    const float* adj   = (const float*)d_in[19];

    float* out = (float*)d_out;
    float* ht_out = out + B_SZ * H_SZ;

    uint32_t* P;
    float *hs, *A, *Bf, *Wt;
    cudaGetSymbolAddress((void**)&P,  g_P);
    cudaGetSymbolAddress((void**)&hs, g_hs);
    cudaGetSymbolAddress((void**)&A,  g_A);
    cudaGetSymbolAddress((void**)&Bf, g_B);
    cudaGetSymbolAddress((void**)&Wt, g_Wt);

    cudaFuncSetAttribute(gru_kernel, cudaFuncAttributeMaxDynamicSharedMemorySize, GRU_SMEM);
    cudaFuncSetAttribute(adjlin_kernel, cudaFuncAttributeMaxDynamicSharedMemorySize, 65536);

    // prep
    pack_whh_kernel<<<(I_SZ * 24576 + 255) / 256, 256>>>(W_hh, P);
    transpose7_kernel<<<(7 * H_SZ * H_SZ + 255) / 256, 256>>>(fp_w, g1_w, g2_w, wk_w, wv_w, wq_w, o0_w, Wt);
    xt_kernel<<<(B_SZ * T_SZ * I_SZ + 255) / 256, 256>>>(x, A);   // A = xT

    const float* fpT = Wt + 0 * 16384;
    const float* g1T = Wt + 1 * 16384;
    const float* g2T = Wt + 2 * 16384;
    const float* wkT = Wt + 3 * 16384;
    const float* wvT = Wt + 4 * 16384;
    const float* wqT = Wt + 5 * 16384;
    const float* o0T = Wt + 6 * 16384;

    // 1) GRU scan -> hs (mma.sync fp16, fp32 accum)
    gru_kernel<<<dim3(16, 64), 256, GRU_SMEM>>>(A, P, W_ih, b_ih, b_hh, hs);

    // 2) ht = hs @ fp^T + b  (straight into d_out)
    lin_kernel<<<B_SZ * I_SZ / 64, 256>>>(hs, fpT, fp_b, ht_out, 0);
    // 3) g = relu((adj @ ht) @ g1^T + b1)
    adjlin_kernel<<<B_SZ, 256, 65536>>>(ht_out, adj, g1T, g1_b, Bf);
    // 4) ctx = relu((adj @ g) @ g2^T + b2)   (A no longer needed as xT)
    adjlin_kernel<<<B_SZ, 256, 65536>>>(Bf, adj, g2T, g2_b, A);
    // 5) K = ctx@wk^T, V = ctx@wv^T (fused)
    kv_kernel<<<B_SZ, 256>>>(A, wkT, wk_b, wvT, wv_b, Bf, hs);
    // 6) attention + head
    attn_kernel<<<B_SZ, 128>>>(A, Bf, hs, wqT, wq_b, o0T, o0_b, out);
}

// round 7
// speedup vs baseline: 9.3591x; 1.2716x over previous
#include <cuda_runtime.h>
#include <cuda_bf16.h>
#include <cuda_fp16.h>
#include <math.h>
#include <stdint.h>

// Problem constants
#define B_SZ 512
#define T_SZ 64
#define I_SZ 64
#define H_SZ 128
#define G_SZ 384   // 3*H

// ---------------- device scratch (no allocations allowed) ----------------
__device__ uint32_t g_P [I_SZ * 24576];             // per-feature W_hh, fp16 B-fragment layout (6MB)
__device__ float g_hs[B_SZ * I_SZ * H_SZ];          // GRU final hidden
__device__ float g_A [B_SZ * I_SZ * H_SZ];          // xT during GRU, then ctx
__device__ float g_B [B_SZ * I_SZ * H_SZ];          // scratch (g)
__device__ float g_Wt[7 * H_SZ * H_SZ];             // transposed tail weights

__device__ __forceinline__ void mma_f16(float* d, const uint32_t* a, uint32_t b0, uint32_t b1) {
    asm volatile(
        "mma.sync.aligned.m16n8k16.row.col.f32.f16.f16.f32 "
        "{%0,%1,%2,%3}, {%4,%5,%6,%7}, {%8,%9}, {%0,%1,%2,%3};"
        : "+f"(d[0]), "+f"(d[1]), "+f"(d[2]), "+f"(d[3])
        : "r"(a[0]), "r"(a[1]), "r"(a[2]), "r"(a[3]), "r"(b0), "r"(b1));
}

__device__ __forceinline__ float tanh_fast(float v) {
    float o;
    asm("tanh.approx.f32 %0, %1;" : "=f"(o) : "f"(v));
    return o;
}

// ---------------- pack W_hh into per-feature fp16 B-fragment layout ----------------
// P[i][ ((w*6+nt)*8+kt)*64 + lane*2 + reg ] = half2( W[gate*128+j][k0], W[...][k0+1] )
// gate=nt>>1 ; j=16w+8(nt&1)+(lane>>2) ; k0=16kt+8reg+2(lane&3)
__global__ void pack_whh_kernel(const float* __restrict__ W_hh, uint32_t* __restrict__ P)
{
    int idx = blockIdx.x * blockDim.x + threadIdx.x;
    if (idx >= I_SZ * 24576) return;
    int i = idx / 24576;
    int r = idx % 24576;
    int w  = r / 3072; r %= 3072;
    int nt = r / 512;  r %= 512;
    int kt = r / 64;   r %= 64;
    int lane = r >> 1;
    int reg  = r & 1;
    int g  = lane >> 2, t4 = lane & 3;
    int k0 = 16 * kt + 8 * reg + 2 * t4;
    int j  = 16 * w + 8 * (nt & 1) + g;
    int gate = nt >> 1;
    const float* src = W_hh + ((size_t)i * G_SZ + gate * 128 + j) * H_SZ + k0;
    __half2 h2 = __floats2half2_rn(src[0], src[1]);
    P[idx] = *reinterpret_cast<uint32_t*>(&h2);
}

// ---------------- transpose x: xT[t][i][b] = x[b][t][i] ----------------
__global__ void xt_kernel(const float* __restrict__ x, float* __restrict__ xT)
{
    int idx = blockIdx.x * blockDim.x + threadIdx.x;
    if (idx >= B_SZ * T_SZ * I_SZ) return;
    int b = idx & 511;
    int r = idx >> 9;
    int i = r & 63;
    int t = r >> 6;
    xT[idx] = x[((size_t)b * T_SZ + t) * I_SZ + i];
}

// ---------------- transpose the 7 [H,H] weight matrices ----------------
__global__ void transpose7_kernel(const float* __restrict__ fp, const float* __restrict__ g1,
                                  const float* __restrict__ g2, const float* __restrict__ wk,
                                  const float* __restrict__ wv, const float* __restrict__ wq,
                                  const float* __restrict__ o0, float* __restrict__ out)
{
    int idx = blockIdx.x * blockDim.x + threadIdx.x;
    if (idx >= 7 * H_SZ * H_SZ) return;
    int w = idx >> 14;
    int r = idx & 16383;
    int k = r >> 7, n = r & 127;
    const float* src = (w == 0) ? fp : (w == 1) ? g1 : (w == 2) ? g2 :
                       (w == 3) ? wk : (w == 4) ? wv : (w == 5) ? wq : o0;
    out[idx] = src[n * 128 + k];
}

// ---------------- GRU scan via mma.sync fp16 (fp32 accum) ----------------
// grid = (16 batch-blocks of 32, 64 features), 256 threads (8 warps)
// warp w owns N-slice j in [16w, 16w+16) x 3 gates, M=32 (2 m-tiles of 16), K=128 (8 kt of 16)
// A-tile double-buffered -> one __syncthreads per step.
#define GRU_SMEM_W 98304                     // 24576 uint32
#define GRU_SMEM   (GRU_SMEM_W + 2 * 8192)   // + 2 x A fragment tile

__global__ __launch_bounds__(256, 2) void gru_kernel(
    const float* __restrict__ xT,     // [T][I][B]
    const uint32_t* __restrict__ P,   // packed W (fp16 fragment layout)
    const float* __restrict__ W_ih,   // [I][3H]
    const float* __restrict__ b_ih,
    const float* __restrict__ b_hh,
    float* __restrict__ hs_out)       // [B][I][H]
{
    extern __shared__ char smem[];
    uint32_t* s_B = (uint32_t*)smem;
    uint4*    s_A0 = (uint4*)(smem + GRU_SMEM_W);
    uint4*    s_A1 = (uint4*)(smem + GRU_SMEM_W + 8192);

    const int i   = blockIdx.y;
    const int b0  = blockIdx.x * 32;
    const int tid = threadIdx.x;
    const int w    = tid >> 5;
    const int lane = tid & 31;
    const int g    = lane >> 2;
    const int t4   = lane & 3;

    // ---- stage W image (96KB) ----
    {
        const uint4* src = (const uint4*)(P + (size_t)i * 24576);
        uint4* dst = (uint4*)s_B;
        for (int idx = tid; idx < 6144; idx += 256) dst[idx] = src[idx];
    }

    // ---- per-thread gate constants (4 j-values) ----
    float wr[4], wz[4], wn[4], ccr[4], ccz[4], bin[4], bhn[4];
#pragma unroll
    for (int p = 0; p < 4; p++) {
        const int j = 16 * w + 8 * (p >> 1) + 2 * t4 + (p & 1);
        const int base = i * G_SZ + j;
        wr[p]  = __ldg(&W_ih[base]);
        wz[p]  = __ldg(&W_ih[base + 128]);
        wn[p]  = __ldg(&W_ih[base + 256]);
        ccr[p] = __ldg(&b_ih[base])       + __ldg(&b_hh[base]);
        ccz[p] = __ldg(&b_ih[base + 128]) + __ldg(&b_hh[base + 128]);
        bin[p] = __ldg(&b_ih[base + 256]);
        bhn[p] = __ldg(&b_hh[base + 256]);
    }

    // h state: h[b = 16mt + g + 8hi][j(p)]
    float hcur[2][4][2];
#pragma unroll
    for (int mt = 0; mt < 2; mt++)
#pragma unroll
        for (int p = 0; p < 4; p++)
            hcur[mt][p][0] = hcur[mt][p][1] = 0.0f;

    __syncthreads();

    const float* xrow = xT + (size_t)i * B_SZ + b0;

    for (int t = 0; t < T_SZ; t++) {
        uint4* s_A = (t & 1) ? s_A1 : s_A0;

        // ---- pack h_t into A-fragment tile (thread writes its own fragment, kt = w) ----
        if (t > 0) {
#pragma unroll
            for (int mt = 0; mt < 2; mt++) {
                uint32_t rr[4];
#pragma unroll
                for (int q = 0; q < 2; q++)
#pragma unroll
                    for (int hi = 0; hi < 2; hi++) {
                        __half2 h2 = __floats2half2_rn(hcur[mt][2 * q][hi], hcur[mt][2 * q + 1][hi]);
                        rr[2 * q + hi] = *reinterpret_cast<uint32_t*>(&h2);
                    }
                s_A[(w * 2 + mt) * 32 + lane] = make_uint4(rr[0], rr[1], rr[2], rr[3]);
            }
        }
        __syncthreads();   // pack visible; double-buffering makes a 2nd barrier unnecessary

        // ---- GEMM: D[2 mt][6 nt][4] += h @ W^T ----
        float D[2][6][4];
#pragma unroll
        for (int mt = 0; mt < 2; mt++)
#pragma unroll
            for (int nt = 0; nt < 6; nt++)
#pragma unroll
                for (int c = 0; c < 4; c++) D[mt][nt][c] = 0.0f;

        if (t > 0) {
#pragma unroll
            for (int kt = 0; kt < 8; kt++) {
                uint4 a0 = s_A[(kt * 2 + 0) * 32 + lane];
                uint4 a1 = s_A[(kt * 2 + 1) * 32 + lane];
                uint32_t af0[4] = {a0.x, a0.y, a0.z, a0.w};
                uint32_t af1[4] = {a1.x, a1.y, a1.z, a1.w};
#pragma unroll
                for (int nt = 0; nt < 6; nt++) {
                    uint2 bv = *(const uint2*)(s_B + ((w * 6 + nt) * 8 + kt) * 64 + lane * 2);
                    mma_f16(D[0][nt], af0, bv.x, bv.y);
                    mma_f16(D[1][nt], af1, bv.x, bv.y);
                }
            }
        }

        // ---- coalesced x loads (1 sector each, L1-resident) ----
        float xv[2][2];
#pragma unroll
        for (int mt = 0; mt < 2; mt++)
#pragma unroll
            for (int hi = 0; hi < 2; hi++)
                xv[mt][hi] = __ldg(xrow + 16 * mt + g + 8 * hi);
        xrow += I_SZ * B_SZ;

        // ---- epilogue: gates via tanh.approx ----
#pragma unroll
        for (int mt = 0; mt < 2; mt++) {
#pragma unroll
            for (int p = 0; p < 4; p++) {
                const int nA = p >> 1, dj = p & 1;
#pragma unroll
                for (int hi = 0; hi < 2; hi++) {
                    const int c = hi * 2 + dj;
                    const float xt = xv[mt][hi];
                    const float ur = fmaf(xt, wr[p], ccr[p]) + D[mt][nA][c];
                    const float uz = fmaf(xt, wz[p], ccz[p]) + D[mt][2 + nA][c];
                    const float r  = fmaf(tanh_fast(0.5f * ur), 0.5f, 0.5f);
                    const float z  = fmaf(tanh_fast(0.5f * uz), 0.5f, 0.5f);
                    const float inn = fmaf(xt, wn[p], bin[p]);
                    const float hn  = D[mt][4 + nA][c] + bhn[p];
                    const float th  = tanh_fast(fmaf(r, hn, inn));
                    hcur[mt][p][hi] = fmaf(z, hcur[mt][p][hi] - th, th);
                }
            }
        }
    }

    // ---- write final hidden state ----
#pragma unroll
    for (int mt = 0; mt < 2; mt++)
#pragma unroll
        for (int p = 0; p < 4; p++) {
            const int j = 16 * w + 8 * (p >> 1) + 2 * t4 + (p & 1);
#pragma unroll
            for (int hi = 0; hi < 2; hi++) {
                const int b = b0 + 16 * mt + g + 8 * hi;
                hs_out[((size_t)b * I_SZ + i) * H_SZ + j] = hcur[mt][p][hi];
            }
        }
}

// ---------------- generic linear: Y = X @ Wt + b ----------------
__global__ __launch_bounds__(256) void lin_kernel(
    const float* __restrict__ X, const float* __restrict__ Wt,
    const float* __restrict__ bias, float* __restrict__ Y, int relu)
{
    __shared__ float Xs[64][128];
    const int m0 = blockIdx.x * 64;
    const int tid = threadIdx.x, w = tid >> 5, l = tid & 31;
    for (int idx = tid; idx < 64 * 128; idx += 256)
        Xs[idx >> 7][idx & 127] = X[(size_t)m0 * 128 + idx];
    __syncthreads();

    float acc[8][4];
#pragma unroll
    for (int rr = 0; rr < 8; rr++)
#pragma unroll
        for (int c = 0; c < 4; c++) acc[rr][c] = 0.f;

    const int r0 = w * 8;
#pragma unroll 4
    for (int k = 0; k < 128; k++) {
        float wv[4];
#pragma unroll
        for (int c = 0; c < 4; c++) wv[c] = __ldg(&Wt[k * 128 + l + 32 * c]);
#pragma unroll
        for (int rr = 0; rr < 8; rr++) {
            const float xv = Xs[r0 + rr][k];
#pragma unroll
            for (int c = 0; c < 4; c++) acc[rr][c] = fmaf(xv, wv[c], acc[rr][c]);
        }
    }
#pragma unroll
    for (int rr = 0; rr < 8; rr++)
#pragma unroll
        for (int c = 0; c < 4; c++) {
            const int n = l + 32 * c;
            float v = acc[rr][c] + __ldg(&bias[n]);
            if (relu) v = fmaxf(v, 0.f);
            Y[(size_t)(m0 + r0 + rr) * 128 + n] = v;
        }
}

// ---------------- fused: Y = relu((adj @ X) @ Wt + b), one block per batch ----------------
__global__ __launch_bounds__(256) void adjlin_kernel(
    const float* __restrict__ X, const float* __restrict__ adj,
    const float* __restrict__ Wt, const float* __restrict__ bias,
    float* __restrict__ Y)
{
    extern __shared__ float sm[];
    float* Xs = sm;           // [64][128]
    float* Zs = sm + 8192;    // [64][128]
    const int b = blockIdx.x;
    const int tid = threadIdx.x, w = tid >> 5, l = tid & 31;
    const int r0 = w * 8;

    for (int idx = tid; idx < 8192; idx += 256)
        Xs[idx] = X[(size_t)b * 8192 + idx];
    __syncthreads();

    // Z = adj @ X
    {
        float acc[8][4];
#pragma unroll
        for (int ii = 0; ii < 8; ii++)
#pragma unroll
            for (int c = 0; c < 4; c++) acc[ii][c] = 0.f;
#pragma unroll 4
        for (int j = 0; j < 64; j++) {
            float hv[4];
#pragma unroll
            for (int c = 0; c < 4; c++) hv[c] = Xs[j * 128 + l + 32 * c];
#pragma unroll
            for (int ii = 0; ii < 8; ii++) {
                const float a = __ldg(&adj[(r0 + ii) * 64 + j]);
#pragma unroll
                for (int c = 0; c < 4; c++) acc[ii][c] = fmaf(a, hv[c], acc[ii][c]);
            }
        }
#pragma unroll
        for (int ii = 0; ii < 8; ii++)
#pragma unroll
            for (int c = 0; c < 4; c++)
                Zs[(r0 + ii) * 128 + l + 32 * c] = acc[ii][c];
    }
    __syncthreads();

    // Y = relu(Z @ Wt + b)
    {
        float acc[8][4];
#pragma unroll
        for (int rr = 0; rr < 8; rr++)
#pragma unroll
            for (int c = 0; c < 4; c++) acc[rr][c] = 0.f;
#pragma unroll 4
        for (int k = 0; k < 128; k++) {
            float wv[4];
#pragma unroll
            for (int c = 0; c < 4; c++) wv[c] = __ldg(&Wt[k * 128 + l + 32 * c]);
#pragma unroll
            for (int rr = 0; rr < 8; rr++) {
                const float xv = Zs[(r0 + rr) * 128 + k];
#pragma unroll
                for (int c = 0; c < 4; c++) acc[rr][c] = fmaf(xv, wv[c], acc[rr][c]);
            }
        }
#pragma unroll
        for (int rr = 0; rr < 8; rr++)
#pragma unroll
            for (int c = 0; c < 4; c++) {
                const int n = l + 32 * c;
                Y[(size_t)b * 8192 + (r0 + rr) * 128 + n] = fmaxf(acc[rr][c] + __ldg(&bias[n]), 0.f);
            }
    }
}

// ---------------- fused attention tail (K/V never materialized) ----------------
// e_i = ctx_i . (Wk^T q) + wk_b . q ;  wctx = Wv (a^T ctx) + wv_b
__global__ __launch_bounds__(128) void attn2_kernel(
    const float* __restrict__ ctx,    // [B][64][128]
    const float* __restrict__ wqT, const float* __restrict__ wq_b,
    const float* __restrict__ wk_w, const float* __restrict__ wk_b,   // original [out][in]
    const float* __restrict__ wvT, const float* __restrict__ wv_b,
    const float* __restrict__ o0T, const float* __restrict__ o0_b,
    float* __restrict__ out)          // [B][128]
{
    __shared__ float Xs[64][129];     // ctx rows (padded vs bank conflicts)
    __shared__ float q[128], u[128], ev[64], red[2], s[128], wc[128];
    const int b = blockIdx.x, t = threadIdx.x;

    for (int idx = t; idx < 8192; idx += 128)
        Xs[idx >> 7][idx & 127] = ctx[(size_t)b * 8192 + idx];
    __syncthreads();

    // q = ctx[63] @ wq^T + b
    {
        float acc = __ldg(&wq_b[t]);
        for (int k = 0; k < 128; k++)
            acc = fmaf(Xs[63][k], __ldg(&wqT[k * 128 + t]), acc);
        q[t] = acc;
    }
    __syncthreads();

    // u[k] = sum_n q[n] * wk[n][k]   (coalesced over t=k)
    {
        float acc = 0.f;
        for (int n = 0; n < 128; n++)
            acc = fmaf(q[n], __ldg(&wk_w[n * 128 + t]), acc);
        u[t] = acc;
    }
    if (t == 0) {
        // c0 = wk_b . q (added to every e_i; shifts cancel in softmax but keep exact)
        float c = 0.f;
        for (int n = 0; n < 128; n++) c = fmaf(q[n], __ldg(&wk_b[n]), c);
        red[0] = c;
    }
    __syncthreads();

    // e_i = c0 + ctx_i . u
    if (t < 64) {
        float e = red[0];
        for (int k = 0; k < 128; k++) e = fmaf(Xs[t][k], u[k], e);
        ev[t] = e;
    }
    __syncthreads();
    if (t == 0) {
        float mx = -1e30f;
        for (int ii = 0; ii < 64; ii++) mx = fmaxf(mx, ev[ii]);
        float sm = 0.f;
        for (int ii = 0; ii < 64; ii++) sm += __expf(ev[ii] - mx);
        red[0] = mx; red[1] = 1.0f / sm;
    }
    __syncthreads();
    if (t < 64) ev[t] = __expf(ev[t] - red[0]) * red[1];
    __syncthreads();

    // s[k] = sum_i a_i ctx_i[k]
    {
        float acc = 0.f;
        for (int ii = 0; ii < 64; ii++) acc = fmaf(ev[ii], Xs[ii][t], acc);
        s[t] = acc;
    }
    __syncthreads();

    // wctx[n] = wv_b[n] + sum_k s[k] wvT[k][n]
    {
        float acc = __ldg(&wv_b[t]);
        for (int k = 0; k < 128; k++) acc = fmaf(s[k], __ldg(&wvT[k * 128 + t]), acc);
        wc[t] = acc;
    }
    __syncthreads();

    // out[n] = relu(o0_b[n] + sum_m wc[m] o0T[m][n])
    {
        float acc = __ldg(&o0_b[t]);
        for (int m = 0; m < 128; m++) acc = fmaf(wc[m], __ldg(&o0T[m * 128 + t]), acc);
        out[(size_t)b * 128 + t] = fmaxf(acc, 0.f);
    }
}

// ---------------- launch ----------------
extern "C" void kernel_launch(void* const* d_in, const int* in_sizes, int n_in,
                              void* d_out, int out_size)
{
    const float* x     = (const float*)d_in[0];
    const float* W_ih  = (const float*)d_in[1];
    const float* W_hh  = (const float*)d_in[2];
    const float* b_ih  = (const float*)d_in[3];
    const float* b_hh  = (const float*)d_in[4];
    const float* fp_w  = (const float*)d_in[5];
    const float* fp_b  = (const float*)d_in[6];
    const float* g1_w  = (const float*)d_in[7];
    const float* g1_b  = (const float*)d_in[8];
    const float* g2_w  = (const float*)d_in[9];
    const float* g2_b  = (const float*)d_in[10];
    const float* wq_w  = (const float*)d_in[11];
    const float* wq_b  = (const float*)d_in[12];
    const float* wk_w  = (const float*)d_in[13];
    const float* wk_b  = (const float*)d_in[14];
    const float* wv_w  = (const float*)d_in[15];
    const float* wv_b  = (const float*)d_in[16];
    const float* o0_w  = (const float*)d_in[17];
    const float* o0_b  = (const float*)d_in[18];
    const float* adj   = (const float*)d_in[19];

    float* out = (float*)d_out;
    float* ht_out = out + B_SZ * H_SZ;

    uint32_t* P;
    float *hs, *A, *Bf, *Wt;
    cudaGetSymbolAddress((void**)&P,  g_P);
    cudaGetSymbolAddress((void**)&hs, g_hs);
    cudaGetSymbolAddress((void**)&A,  g_A);
    cudaGetSymbolAddress((void**)&Bf, g_B);
    cudaGetSymbolAddress((void**)&Wt, g_Wt);

    cudaFuncSetAttribute(gru_kernel, cudaFuncAttributeMaxDynamicSharedMemorySize, GRU_SMEM);
    cudaFuncSetAttribute(adjlin_kernel, cudaFuncAttributeMaxDynamicSharedMemorySize, 65536);

    // prep
    pack_whh_kernel<<<(I_SZ * 24576 + 255) / 256, 256>>>(W_hh, P);
    transpose7_kernel<<<(7 * H_SZ * H_SZ + 255) / 256, 256>>>(fp_w, g1_w, g2_w, wk_w, wv_w, wq_w, o0_w, Wt);
    xt_kernel<<<(B_SZ * T_SZ * I_SZ + 255) / 256, 256>>>(x, A);   // A = xT

    const float* fpT = Wt + 0 * 16384;
    const float* g1T = Wt + 1 * 16384;
    const float* g2T = Wt + 2 * 16384;
    const float* wvT = Wt + 4 * 16384;
    const float* wqT = Wt + 5 * 16384;
    const float* o0T = Wt + 6 * 16384;

    // 1) GRU scan -> hs (mma.sync fp16, fp32 accum)
    gru_kernel<<<dim3(16, 64), 256, GRU_SMEM>>>(A, P, W_ih, b_ih, b_hh, hs);

    // 2) ht = hs @ fp^T + b  (straight into d_out)
    lin_kernel<<<B_SZ * I_SZ / 64, 256>>>(hs, fpT, fp_b, ht_out, 0);
    // 3) g = relu((adj @ ht) @ g1^T + b1)
    adjlin_kernel<<<B_SZ, 256, 65536>>>(ht_out, adj, g1T, g1_b, Bf);
    // 4) ctx = relu((adj @ g) @ g2^T + b2)
    adjlin_kernel<<<B_SZ, 256, 65536>>>(Bf, adj, g2T, g2_b, A);
    // 5+6) fused attention tail
    attn2_kernel<<<B_SZ, 128>>>(A, wqT, wq_b, wk_w, wk_b, wvT, wv_b, o0T, o0_b, out);
}

// round 8
// speedup vs baseline: 9.7609x; 1.0429x over previous
#include <cuda_runtime.h>
#include <cuda_bf16.h>
#include <cuda_fp16.h>
#include <math.h>
#include <stdint.h>

// Problem constants
#define B_SZ 512
#define T_SZ 64
#define I_SZ 64
#define H_SZ 128
#define G_SZ 384   // 3*H

// ---------------- device scratch (no allocations allowed) ----------------
__device__ uint32_t g_P [I_SZ * 24576];             // per-feature W_hh, fp16 paired-fragment layout
__device__ float g_hs[B_SZ * I_SZ * H_SZ];          // GRU final hidden
__device__ float g_A [B_SZ * I_SZ * H_SZ];          // xT
__device__ float g_Wt[7 * H_SZ * H_SZ];             // transposed tail weights

__device__ __forceinline__ void mma_f16(float* d, const uint32_t* a, uint32_t b0, uint32_t b1) {
    asm volatile(
        "mma.sync.aligned.m16n8k16.row.col.f32.f16.f16.f32 "
        "{%0,%1,%2,%3}, {%4,%5,%6,%7}, {%8,%9}, {%0,%1,%2,%3};"
        : "+f"(d[0]), "+f"(d[1]), "+f"(d[2]), "+f"(d[3])
        : "r"(a[0]), "r"(a[1]), "r"(a[2]), "r"(a[3]), "r"(b0), "r"(b1));
}

__device__ __forceinline__ __half2 tanh2(__half2 v) {
    uint32_t o, in = *reinterpret_cast<uint32_t*>(&v);
    asm("tanh.approx.f16x2 %0, %1;" : "=r"(o) : "r"(in));
    return *reinterpret_cast<__half2*>(&o);
}

// ---------------- pack W_hh: fp16, nA-paired B-fragment layout, r/z rows pre-scaled 0.5 ----------------
// P[i][ (((w*3+g3)*8+kt)*32 + lane)*4 + s ], s: nA = s>>1, reg = s&1
// k0 = 16kt + 8reg + 2(lane&3) ; j = 16w + 8nA + (lane>>2) ; row = g3*128 + j
__global__ void pack_whh_kernel(const float* __restrict__ W_hh, uint32_t* __restrict__ P)
{
    int idx = blockIdx.x * blockDim.x + threadIdx.x;
    if (idx >= I_SZ * 24576) return;
    int i = idx / 24576;
    int r = idx % 24576;
    int w  = r / 3072; r %= 3072;
    int g3 = r / 1024; r %= 1024;
    int kt = r / 128;  r %= 128;
    int lane = r >> 2;
    int s = r & 3;
    int nA = s >> 1, reg = s & 1;
    int k0 = 16 * kt + 8 * reg + 2 * (lane & 3);
    int j  = 16 * w + 8 * nA + (lane >> 2);
    float scale = (g3 < 2) ? 0.5f : 1.0f;   // fold sigmoid's /2 into r,z weights
    const float* src = W_hh + ((size_t)i * G_SZ + g3 * 128 + j) * H_SZ + k0;
    __half2 h2 = __floats2half2_rn(scale * src[0], scale * src[1]);
    P[idx] = *reinterpret_cast<uint32_t*>(&h2);
}

// ---------------- transpose x: xT[t][i][b] = x[b][t][i] ----------------
__global__ void xt_kernel(const float* __restrict__ x, float* __restrict__ xT)
{
    int idx = blockIdx.x * blockDim.x + threadIdx.x;
    if (idx >= B_SZ * T_SZ * I_SZ) return;
    int b = idx & 511;
    int r = idx >> 9;
    int i = r & 63;
    int t = r >> 6;
    xT[idx] = x[((size_t)b * T_SZ + t) * I_SZ + i];
}

// ---------------- transpose the 7 [H,H] weight matrices ----------------
__global__ void transpose7_kernel(const float* __restrict__ fp, const float* __restrict__ g1,
                                  const float* __restrict__ g2, const float* __restrict__ wk,
                                  const float* __restrict__ wv, const float* __restrict__ wq,
                                  const float* __restrict__ o0, float* __restrict__ out)
{
    int idx = blockIdx.x * blockDim.x + threadIdx.x;
    if (idx >= 7 * H_SZ * H_SZ) return;
    int w = idx >> 14;
    int r = idx & 16383;
    int k = r >> 7, n = r & 127;
    const float* src = (w == 0) ? fp : (w == 1) ? g1 : (w == 2) ? g2 :
                       (w == 3) ? wk : (w == 4) ? wv : (w == 5) ? wq : o0;
    out[idx] = src[n * 128 + k];
}

// ---------------- GRU scan via mma.sync fp16 + f16x2 epilogue ----------------
#define GRU_SMEM_W 98304
#define GRU_SMEM   (GRU_SMEM_W + 2 * 8192)

__global__ __launch_bounds__(256, 2) void gru_kernel(
    const float* __restrict__ xT,     // [T][I][B]
    const uint32_t* __restrict__ P,
    const float* __restrict__ W_ih,   // [I][3H]
    const float* __restrict__ b_ih,
    const float* __restrict__ b_hh,
    float* __restrict__ hs_out)       // [B][I][H]
{
    extern __shared__ char smem[];
    uint4* s_B  = (uint4*)smem;
    uint4* s_A0 = (uint4*)(smem + GRU_SMEM_W);
    uint4* s_A1 = (uint4*)(smem + GRU_SMEM_W + 8192);

    const int i   = blockIdx.y;
    const int b0  = blockIdx.x * 32;
    const int tid = threadIdx.x;
    const int w    = tid >> 5;
    const int lane = tid & 31;
    const int g    = lane >> 2;
    const int t4   = lane & 3;

    // ---- stage W image (96KB) ----
    {
        const uint4* src = (const uint4*)(P + (size_t)i * 24576);
        for (int idx = tid; idx < 6144; idx += 256) s_B[idx] = src[idx];
    }

    // ---- per-thread gate constants (p = 2*nA + dj), r/z scaled by 0.5 ----
    float wr[4], wz[4], wn[4], bin[4], CC[3][4];
#pragma unroll
    for (int p = 0; p < 4; p++) {
        const int j = 16 * w + 8 * (p >> 1) + 2 * t4 + (p & 1);
        const int base = i * G_SZ + j;
        wr[p]  = 0.5f * __ldg(&W_ih[base]);
        wz[p]  = 0.5f * __ldg(&W_ih[base + 128]);
        wn[p]  = __ldg(&W_ih[base + 256]);
        CC[0][p] = 0.5f * (__ldg(&b_ih[base])       + __ldg(&b_hh[base]));
        CC[1][p] = 0.5f * (__ldg(&b_ih[base + 128]) + __ldg(&b_hh[base + 128]));
        CC[2][p] = __ldg(&b_hh[base + 256]);
        bin[p] = __ldg(&b_ih[base + 256]);
    }

    // h state as half2 pairs over dj: hq[mt][nA][hi]
    __half2 hq[2][2][2];
    const __half2 hzero = __float2half2_rn(0.0f);
    const __half2 hhalf = __float2half2_rn(0.5f);
#pragma unroll
    for (int mt = 0; mt < 2; mt++)
#pragma unroll
        for (int q = 0; q < 2; q++)
            hq[mt][q][0] = hq[mt][q][1] = hzero;

    __syncthreads();

    const float* xrow = xT + (size_t)i * B_SZ + b0;

    for (int t = 0; t < T_SZ; t++) {
        uint4* s_A = (t & 1) ? s_A1 : s_A0;

        // ---- pack h_t (already half2 in fragment order) ----
        if (t > 0) {
#pragma unroll
            for (int mt = 0; mt < 2; mt++) {
                uint4 v;
                v.x = *reinterpret_cast<uint32_t*>(&hq[mt][0][0]);
                v.y = *reinterpret_cast<uint32_t*>(&hq[mt][0][1]);
                v.z = *reinterpret_cast<uint32_t*>(&hq[mt][1][0]);
                v.w = *reinterpret_cast<uint32_t*>(&hq[mt][1][1]);
                s_A[(w * 2 + mt) * 32 + lane] = v;
            }
        }
        __syncthreads();

        // ---- D init with gate constants (indep of mt/hi) ----
        float D[2][6][4];
#pragma unroll
        for (int mt = 0; mt < 2; mt++)
#pragma unroll
            for (int g3 = 0; g3 < 3; g3++)
#pragma unroll
                for (int q = 0; q < 2; q++) {
                    D[mt][2 * g3 + q][0] = CC[g3][2 * q];
                    D[mt][2 * g3 + q][1] = CC[g3][2 * q + 1];
                    D[mt][2 * g3 + q][2] = CC[g3][2 * q];
                    D[mt][2 * g3 + q][3] = CC[g3][2 * q + 1];
                }

        if (t > 0) {
#pragma unroll
            for (int kt = 0; kt < 8; kt++) {
                uint4 a0 = s_A[(kt * 2 + 0) * 32 + lane];
                uint4 a1 = s_A[(kt * 2 + 1) * 32 + lane];
                uint32_t af0[4] = {a0.x, a0.y, a0.z, a0.w};
                uint32_t af1[4] = {a1.x, a1.y, a1.z, a1.w};
#pragma unroll
                for (int g3 = 0; g3 < 3; g3++) {
                    uint4 bv = s_B[((w * 3 + g3) * 8 + kt) * 32 + lane];
                    mma_f16(D[0][2 * g3 + 0], af0, bv.x, bv.y);
                    mma_f16(D[0][2 * g3 + 1], af0, bv.z, bv.w);
                    mma_f16(D[1][2 * g3 + 0], af1, bv.x, bv.y);
                    mma_f16(D[1][2 * g3 + 1], af1, bv.z, bv.w);
                }
            }
        }

        // ---- x loads ----
        float xv[2][2];
#pragma unroll
        for (int mt = 0; mt < 2; mt++)
#pragma unroll
            for (int hi = 0; hi < 2; hi++)
                xv[mt][hi] = __ldg(xrow + 16 * mt + g + 8 * hi);
        xrow += I_SZ * B_SZ;

        // ---- epilogue: f16x2 gates (pairs over dj) ----
#pragma unroll
        for (int mt = 0; mt < 2; mt++) {
#pragma unroll
            for (int hi = 0; hi < 2; hi++) {
                const float xt = xv[mt][hi];
                const int c0 = 2 * hi, c1 = 2 * hi + 1;
#pragma unroll
                for (int q = 0; q < 2; q++) {
                    const int p0 = 2 * q, p1 = 2 * q + 1;
                    // r gate (pre-scaled by 0.5): sigmoid = 0.5 + 0.5*tanh
                    const float ur0 = fmaf(xt, wr[p0], D[mt][q][c0]);
                    const float ur1 = fmaf(xt, wr[p1], D[mt][q][c1]);
                    const __half2 r2 = __hfma2(tanh2(__floats2half2_rn(ur0, ur1)), hhalf, hhalf);
                    // z gate
                    const float uz0 = fmaf(xt, wz[p0], D[mt][2 + q][c0]);
                    const float uz1 = fmaf(xt, wz[p1], D[mt][2 + q][c1]);
                    const __half2 z2 = __hfma2(tanh2(__floats2half2_rn(uz0, uz1)), hhalf, hhalf);
                    // n candidate: tanh(inn + r*hn)
                    const float in0 = fmaf(xt, wn[p0], bin[p0]);
                    const float in1 = fmaf(xt, wn[p1], bin[p1]);
                    const __half2 inn2 = __floats2half2_rn(in0, in1);
                    const __half2 hn2  = __floats2half2_rn(D[mt][4 + q][c0], D[mt][4 + q][c1]);
                    const __half2 th2  = tanh2(__hfma2(r2, hn2, inn2));
                    // h = z*(h - n) + n
                    const __half2 hold = hq[mt][q][hi];
                    hq[mt][q][hi] = __hfma2(z2, __hsub2(hold, th2), th2);
                }
            }
        }
    }

    // ---- write final hidden state ----
#pragma unroll
    for (int mt = 0; mt < 2; mt++)
#pragma unroll
        for (int q = 0; q < 2; q++) {
            const int j = 16 * w + 8 * q + 2 * t4;
#pragma unroll
            for (int hi = 0; hi < 2; hi++) {
                const int b = b0 + 16 * mt + g + 8 * hi;
                float2 f = __half22float2(hq[mt][q][hi]);
                float* dst = hs_out + ((size_t)b * I_SZ + i) * H_SZ + j;
                dst[0] = f.x;
                dst[1] = f.y;
            }
        }
}

// ---------------- fused tail helpers (smem-resident per-batch pipeline) ----------------
__device__ __forceinline__ void lin_smem(const float* __restrict__ Xin, const float* __restrict__ Wt,
                                         const float* __restrict__ bias, float* __restrict__ Yout,
                                         float* __restrict__ gout, int relu, int w, int l)
{
    const int r0 = w * 8;
    float acc[8][4];
#pragma unroll
    for (int rr = 0; rr < 8; rr++)
#pragma unroll
        for (int c = 0; c < 4; c++) acc[rr][c] = 0.f;
#pragma unroll 4
    for (int k = 0; k < 128; k++) {
        float wv[4];
#pragma unroll
        for (int c = 0; c < 4; c++) wv[c] = __ldg(&Wt[k * 128 + l + 32 * c]);
#pragma unroll
        for (int rr = 0; rr < 8; rr++) {
            const float xv = Xin[(r0 + rr) * 128 + k];
#pragma unroll
            for (int c = 0; c < 4; c++) acc[rr][c] = fmaf(xv, wv[c], acc[rr][c]);
        }
    }
#pragma unroll
    for (int rr = 0; rr < 8; rr++)
#pragma unroll
        for (int c = 0; c < 4; c++) {
            const int n = l + 32 * c;
            float v = acc[rr][c] + __ldg(&bias[n]);
            if (relu) v = fmaxf(v, 0.f);
            Yout[(r0 + rr) * 128 + n] = v;
            if (gout) gout[(size_t)(r0 + rr) * 128 + n] = v;
        }
}

__device__ __forceinline__ void adj_smem(const float* __restrict__ Xin, const float* __restrict__ adj,
                                         float* __restrict__ Yout, int w, int l)
{
    const int i0 = w * 8;
    float acc[8][4];
#pragma unroll
    for (int ii = 0; ii < 8; ii++)
#pragma unroll
        for (int c = 0; c < 4; c++) acc[ii][c] = 0.f;
#pragma unroll 4
    for (int j = 0; j < 64; j++) {
        float hv[4];
#pragma unroll
        for (int c = 0; c < 4; c++) hv[c] = Xin[j * 128 + l + 32 * c];
#pragma unroll
        for (int ii = 0; ii < 8; ii++) {
            const float a = __ldg(&adj[(i0 + ii) * 64 + j]);
#pragma unroll
            for (int c = 0; c < 4; c++) acc[ii][c] = fmaf(a, hv[c], acc[ii][c]);
        }
    }
#pragma unroll
    for (int ii = 0; ii < 8; ii++)
#pragma unroll
        for (int c = 0; c < 4; c++)
            Yout[(i0 + ii) * 128 + l + 32 * c] = acc[ii][c];
}

// one block per batch: hs -> ht(out) -> adj -> g1 -> adj -> g2 -> attention -> out
#define TAIL_SMEM (16384 * 4 + 4 * (128 * 4 + 64 + 2) + 256)

__global__ __launch_bounds__(256) void tail_kernel(
    const float* __restrict__ hs, const float* __restrict__ adj,
    const float* __restrict__ fpT, const float* __restrict__ fp_b,
    const float* __restrict__ g1T, const float* __restrict__ g1_b,
    const float* __restrict__ g2T, const float* __restrict__ g2_b,
    const float* __restrict__ wqT, const float* __restrict__ wq_b,
    const float* __restrict__ wk_w, const float* __restrict__ wk_b,
    const float* __restrict__ wvT, const float* __restrict__ wv_b,
    const float* __restrict__ o0T, const float* __restrict__ o0_b,
    float* __restrict__ ht_out, float* __restrict__ out)
{
    extern __shared__ float sm[];
    float* Xs = sm;                  // [64][128]
    float* Zs = sm + 8192;           // [64][128]
    float* q  = sm + 16384;
    float* u  = q + 128;
    float* s  = u + 128;
    float* wc = s + 128;
    float* ev = wc + 128;
    float* red = ev + 64;

    const int b = blockIdx.x;
    const int tid = threadIdx.x, w = tid >> 5, l = tid & 31;

    for (int idx = tid; idx < 8192; idx += 256)
        Xs[idx] = hs[(size_t)b * 8192 + idx];
    __syncthreads();

    // ht = hs @ fpT + fp_b (write to d_out too)
    lin_smem(Xs, fpT, fp_b, Zs, ht_out + (size_t)b * 8192, 0, w, l);
    __syncthreads();
    adj_smem(Zs, adj, Xs, w, l);
    __syncthreads();
    lin_smem(Xs, g1T, g1_b, Zs, nullptr, 1, w, l);
    __syncthreads();
    adj_smem(Zs, adj, Xs, w, l);
    __syncthreads();
    lin_smem(Xs, g2T, g2_b, Zs, nullptr, 1, w, l);   // Zs = ctx
    __syncthreads();

    // ---- attention on ctx (Zs) ----
    if (tid < 128) {
        float acc = __ldg(&wq_b[tid]);
        for (int k = 0; k < 128; k++)
            acc = fmaf(Zs[63 * 128 + k], __ldg(&wqT[k * 128 + tid]), acc);
        q[tid] = acc;
    }
    __syncthreads();
    if (tid < 128) {
        float acc = 0.f;
        for (int n = 0; n < 128; n++)
            acc = fmaf(q[n], __ldg(&wk_w[n * 128 + tid]), acc);
        u[tid] = acc;
    }
    if (tid == 128 || (tid == 0 && blockDim.x <= 128)) {
        float c = 0.f;
        for (int n = 0; n < 128; n++) c = fmaf(q[n], __ldg(&wk_b[n]), c);
        red[0] = c;
    }
    __syncthreads();
    if (tid < 64) {
        float e = red[0];
        for (int k = 0; k < 128; k++) e = fmaf(Zs[tid * 128 + k], u[k], e);
        ev[tid] = e;
    }
    __syncthreads();
    if (tid == 0) {
        float mx = -1e30f;
        for (int ii = 0; ii < 64; ii++) mx = fmaxf(mx, ev[ii]);
        float smm = 0.f;
        for (int ii = 0; ii < 64; ii++) smm += __expf(ev[ii] - mx);
        red[0] = mx; red[1] = 1.0f / smm;
    }
    __syncthreads();
    if (tid < 64) ev[tid] = __expf(ev[tid] - red[0]) * red[1];
    __syncthreads();
    if (tid < 128) {
        float acc = 0.f;
        for (int ii = 0; ii < 64; ii++) acc = fmaf(ev[ii], Zs[ii * 128 + tid], acc);
        s[tid] = acc;
    }
    __syncthreads();
    if (tid < 128) {
        float acc = __ldg(&wv_b[tid]);
        for (int k = 0; k < 128; k++) acc = fmaf(s[k], __ldg(&wvT[k * 128 + tid]), acc);
        wc[tid] = acc;
    }
    __syncthreads();
    if (tid < 128) {
        float acc = __ldg(&o0_b[tid]);
        for (int m = 0; m < 128; m++) acc = fmaf(wc[m], __ldg(&o0T[m * 128 + tid]), acc);
        out[(size_t)b * 128 + tid] = fmaxf(acc, 0.f);
    }
}

// ---------------- launch ----------------
extern "C" void kernel_launch(void* const* d_in, const int* in_sizes, int n_in,
                              void* d_out, int out_size)
{
    const float* x     = (const float*)d_in[0];
    const float* W_ih  = (const float*)d_in[1];
    const float* W_hh  = (const float*)d_in[2];
    const float* b_ih  = (const float*)d_in[3];
    const float* b_hh  = (const float*)d_in[4];
    const float* fp_w  = (const float*)d_in[5];
    const float* fp_b  = (const float*)d_in[6];
    const float* g1_w  = (const float*)d_in[7];
    const float* g1_b  = (const float*)d_in[8];
    const float* g2_w  = (const float*)d_in[9];
    const float* g2_b  = (const float*)d_in[10];
    const float* wq_w  = (const float*)d_in[11];
    const float* wq_b  = (const float*)d_in[12];
    const float* wk_w  = (const float*)d_in[13];
    const float* wk_b  = (const float*)d_in[14];
    const float* wv_w  = (const float*)d_in[15];
    const float* wv_b  = (const float*)d_in[16];
    const float* o0_w  = (const float*)d_in[17];
    const float* o0_b  = (const float*)d_in[18];
    const float* adj   = (const float*)d_in[19];

    float* out = (float*)d_out;
    float* ht_out = out + B_SZ * H_SZ;

    uint32_t* P;
    float *hs, *A, *Wt;
    cudaGetSymbolAddress((void**)&P,  g_P);
    cudaGetSymbolAddress((void**)&hs, g_hs);
    cudaGetSymbolAddress((void**)&A,  g_A);
    cudaGetSymbolAddress((void**)&Wt, g_Wt);

    cudaFuncSetAttribute(gru_kernel, cudaFuncAttributeMaxDynamicSharedMemorySize, GRU_SMEM);
    cudaFuncSetAttribute(tail_kernel, cudaFuncAttributeMaxDynamicSharedMemorySize, TAIL_SMEM);

    // prep
    pack_whh_kernel<<<(I_SZ * 24576 + 255) / 256, 256>>>(W_hh, P);
    transpose7_kernel<<<(7 * H_SZ * H_SZ + 255) / 256, 256>>>(fp_w, g1_w, g2_w, wk_w, wv_w, wq_w, o0_w, Wt);
    xt_kernel<<<(B_SZ * T_SZ * I_SZ + 255) / 256, 256>>>(x, A);

    const float* fpT = Wt + 0 * 16384;
    const float* g1T = Wt + 1 * 16384;
    const float* g2T = Wt + 2 * 16384;
    const float* wvT = Wt + 4 * 16384;
    const float* wqT = Wt + 5 * 16384;
    const float* o0T = Wt + 6 * 16384;

    // 1) GRU scan -> hs
    gru_kernel<<<dim3(16, 64), 256, GRU_SMEM>>>(A, P, W_ih, b_ih, b_hh, hs);

    // 2) fused tail: ht + graph convs + attention + head
    tail_kernel<<<B_SZ, 256, TAIL_SMEM>>>(hs, adj,
                                          fpT, fp_b, g1T, g1_b, g2T, g2_b,
                                          wqT, wq_b, wk_w, wk_b, wvT, wv_b,
                                          o0T, o0_b, ht_out, out);
}